// round 5
// baseline (speedup 1.0000x reference)
#include <cuda_runtime.h>
#include <cstdint>

#define N_NODES 100000
#define N_ROWS_PAD 100096              // 782 * 128
#define N_EDGES 1600000
#define HID     128
#define IN_DIM  16
#define LN_EPS  1e-5f
#define SCAN_B  512

// ---------------- device scratch ----------------
__device__ int   g_deg[N_NODES];
__device__ float g_dis[N_NODES];
__device__ int   g_off[N_NODES + 1];
__device__ int2  g_csr[N_EDGES];
__device__ float g_h[(size_t)N_NODES * HID];
__device__ float g_p[(size_t)N_ROWS_PAD * HID];   // padded, .bss zeros
__device__ int   g_bsum[256];
__device__ int   g_wide;

// ---------------- tf32 helpers (non-'a' ISA, sm_80+) ----------------
__device__ __forceinline__ uint32_t to_tf32(float v) {
    uint32_t b;
    asm("cvt.rna.tf32.f32 %0, %1;" : "=r"(b) : "f"(v));
    return b;
}
__device__ __forceinline__ void mma_tf32(float c[4], uint32_t a0, uint32_t a1,
                                         uint32_t a2, uint32_t a3,
                                         uint32_t b0, uint32_t b1) {
    asm("mma.sync.aligned.m16n8k8.row.col.f32.tf32.tf32.f32 "
        "{%0,%1,%2,%3}, {%4,%5,%6,%7}, {%8,%9}, {%0,%1,%2,%3};"
        : "+f"(c[0]), "+f"(c[1]), "+f"(c[2]), "+f"(c[3])
        : "r"(a0), "r"(a1), "r"(a2), "r"(a3), "r"(b0), "r"(b1));
}

// ---------------- edge dtype detection ----------------
__global__ void k_detect(const unsigned int* __restrict__ e32, int nwords) {
    __shared__ unsigned int s_or;
    if (threadIdx.x == 0) s_or = 0u;
    __syncthreads();
    unsigned int v = 0u;
    for (int i = threadIdx.x * 2 + 1; i < nwords; i += blockDim.x * 2) v |= e32[i];
    atomicOr(&s_or, v);
    __syncthreads();
    if (threadIdx.x == 0) g_wide = (s_or == 0u) ? 1 : 0;
}

__device__ __forceinline__ int load_edge(const void* eidx, long idx, int wide) {
    if (wide) return (int)((const long long*)eidx)[idx];
    return ((const int*)eidx)[idx];
}

// ---------------- CSR build ----------------
__global__ void k_zero() {
    int i = blockIdx.x * blockDim.x + threadIdx.x;
    if (i < N_NODES) g_deg[i] = 0;
}
__global__ void k_hist(const void* __restrict__ eidx, int E) {
    int i = blockIdx.x * blockDim.x + threadIdx.x;
    if (i >= E) return;
    atomicAdd(&g_deg[load_edge(eidx, (long)E + i, g_wide)], 1);
}
__global__ void k_scan1() {
    __shared__ int s[SCAN_B];
    int tid = threadIdx.x;
    int i = blockIdx.x * SCAN_B + tid;
    s[tid] = (i < N_NODES) ? g_deg[i] : 0;
    __syncthreads();
    for (int o = SCAN_B / 2; o > 0; o >>= 1) {
        if (tid < o) s[tid] += s[tid + o];
        __syncthreads();
    }
    if (tid == 0) g_bsum[blockIdx.x] = s[0];
}
__global__ void k_scan2(int nb) {
    __shared__ int s[256];
    int tid = threadIdx.x;
    int v = (tid < nb) ? g_bsum[tid] : 0;
    s[tid] = v;
    __syncthreads();
    for (int o = 1; o < 256; o <<= 1) {
        int t = (tid >= o) ? s[tid - o] : 0;
        __syncthreads();
        s[tid] += t;
        __syncthreads();
    }
    if (tid < nb) g_bsum[tid] = s[tid] - v;
}
__global__ void k_scan3() {
    __shared__ int s[SCAN_B];
    int tid = threadIdx.x;
    int i = blockIdx.x * SCAN_B + tid;
    int v = (i < N_NODES) ? g_deg[i] : 0;
    s[tid] = v;
    __syncthreads();
    for (int o = 1; o < SCAN_B; o <<= 1) {
        int t = (tid >= o) ? s[tid - o] : 0;
        __syncthreads();
        s[tid] += t;
        __syncthreads();
    }
    int off = g_bsum[blockIdx.x] + s[tid] - v;
    if (i < N_NODES) {
        g_off[i] = off;
        g_dis[i] = rsqrtf((float)(v + 1));
        if (i == N_NODES - 1) g_off[N_NODES] = off + v;
        g_deg[i] = off;
    }
}
__global__ void k_fill(const void* __restrict__ eidx, int E) {
    int i = blockIdx.x * blockDim.x + threadIdx.x;
    if (i >= E) return;
    int wide = g_wide;
    int sidx = load_edge(eidx, i, wide);
    int didx = load_edge(eidx, (long)E + i, wide);
    int pos = atomicAdd(&g_deg[didx], 1);
    g_csr[pos] = make_int2(sidx, __float_as_int(g_dis[sidx]));
}

// ---------------- input projection ----------------
__global__ void k_proj(const float* __restrict__ x, const float* __restrict__ Win,
                       const float* __restrict__ bin) {
    __shared__ float sW[IN_DIM * HID];
    __shared__ float sx[8 * IN_DIM];
    int tid = threadIdx.x;
    for (int i = tid; i < IN_DIM * HID; i += 128) sW[i] = Win[i];
    int base = blockIdx.x * 8;
    {
        int n = tid / IN_DIM, k = tid % IN_DIM;
        int node = base + n;
        sx[tid] = (node < N_NODES) ? x[(size_t)node * IN_DIM + k] : 0.f;
    }
    __syncthreads();
    float bc = bin[tid];
    for (int n = 0; n < 8; n++) {
        int node = base + n;
        if (node >= N_NODES) break;
        float sum = bc;
#pragma unroll
        for (int k = 0; k < IN_DIM; k++) sum += sx[n * IN_DIM + k] * sW[k * HID + tid];
        g_h[(size_t)node * HID + tid] = sum;
    }
}

// ---------------- propagate (MLP=4 gather) ----------------
__global__ void k_gather() {
    int warp = threadIdx.x >> 5, lane = threadIdx.x & 31;
    int d = blockIdx.x * 8 + warp;
    if (d >= N_NODES) return;
    int start = g_off[d], end = g_off[d + 1];
    float dd = g_dis[d];
    const float4* hv = (const float4*)g_h;
    float4 acc = hv[(size_t)d * 32 + lane];
    acc.x *= dd; acc.y *= dd; acc.z *= dd; acc.w *= dd;
    for (int j = start; j < end; j += 32) {
        int2 ew = make_int2(0, 0);
        if (j + lane < end) ew = g_csr[j + lane];
        int cnt = min(32, end - j);
        int t = 0;
        for (; t + 4 <= cnt; t += 4) {
            int s0 = __shfl_sync(0xffffffffu, ew.x, t);
            int s1 = __shfl_sync(0xffffffffu, ew.x, t + 1);
            int s2 = __shfl_sync(0xffffffffu, ew.x, t + 2);
            int s3 = __shfl_sync(0xffffffffu, ew.x, t + 3);
            float w0 = __int_as_float(__shfl_sync(0xffffffffu, ew.y, t));
            float w1 = __int_as_float(__shfl_sync(0xffffffffu, ew.y, t + 1));
            float w2 = __int_as_float(__shfl_sync(0xffffffffu, ew.y, t + 2));
            float w3 = __int_as_float(__shfl_sync(0xffffffffu, ew.y, t + 3));
            float4 v0 = hv[(size_t)s0 * 32 + lane];
            float4 v1 = hv[(size_t)s1 * 32 + lane];
            float4 v2 = hv[(size_t)s2 * 32 + lane];
            float4 v3 = hv[(size_t)s3 * 32 + lane];
            acc.x += w0 * v0.x; acc.y += w0 * v0.y; acc.z += w0 * v0.z; acc.w += w0 * v0.w;
            acc.x += w1 * v1.x; acc.y += w1 * v1.y; acc.z += w1 * v1.z; acc.w += w1 * v1.w;
            acc.x += w2 * v2.x; acc.y += w2 * v2.y; acc.z += w2 * v2.z; acc.w += w2 * v2.w;
            acc.x += w3 * v3.x; acc.y += w3 * v3.y; acc.z += w3 * v3.z; acc.w += w3 * v3.w;
        }
        for (; t < cnt; t++) {
            int   s = __shfl_sync(0xffffffffu, ew.x, t);
            float w = __int_as_float(__shfl_sync(0xffffffffu, ew.y, t));
            float4 v = hv[(size_t)s * 32 + lane];
            acc.x += w * v.x; acc.y += w * v.y; acc.z += w * v.z; acc.w += w * v.w;
        }
    }
    acc.x *= dd; acc.y *= dd; acc.z *= dd; acc.w *= dd;
    ((float4*)g_p)[(size_t)d * 32 + lane] = acc;
}

// ---------------- transform via mma.sync tf32 (A error-split) ----------------
// Block: 128-row tile, 256 threads = 8 warps; warp w owns rows [16w, 16w+16).
// smem (dynamic, stride 132 u32 per row):
//   sAhi [128x132]  tf32(p)
//   sAlo [128x132]  tf32(p - tf32(p))
//   sW   [128x132]  tf32(W), layout [k][n]
// sAhi region reused as f32 staging sO after the mainloop.
#define TSTRIDE 132
#define SM_AHI 0
#define SM_ALO (128 * TSTRIDE)
#define SM_W   (256 * TSTRIDE)
#define SM_U32_TOTAL (384 * TSTRIDE)

__global__ void __launch_bounds__(256) k_transform_tc(
        const float* __restrict__ W, const float* __restrict__ bias,
        const float* __restrict__ gamma, const float* __restrict__ beta,
        float* __restrict__ out, int add_res) {
    extern __shared__ uint32_t smem[];
    __shared__ float sBias[HID], sG[HID], sBe[HID];
    int tid = threadIdx.x;
    int rbase = blockIdx.x * 128;

    for (int i = tid; i < HID; i += 256) {
        sBias[i] = bias[i];
        sG[i] = gamma[i];
        sBe[i] = beta[i];
    }
    // stage W: [k][n] -> sW[k*132+n], tf32
    for (int i = tid; i < HID * HID; i += 256) {
        int k = i >> 7, n = i & 127;
        smem[SM_W + k * TSTRIDE + n] = to_tf32(W[i]);
    }
    // stage A hi/lo from g_p
    {
        const float4* p4 = (const float4*)g_p;
        for (int i = tid; i < 128 * 32; i += 256) {
            int r = i >> 5, c4 = i & 31;
            float4 v = p4[(size_t)(rbase + r) * 32 + c4];
            uint4 hi, lo;
            hi.x = to_tf32(v.x); lo.x = to_tf32(v.x - __uint_as_float(hi.x));
            hi.y = to_tf32(v.y); lo.y = to_tf32(v.y - __uint_as_float(hi.y));
            hi.z = to_tf32(v.z); lo.z = to_tf32(v.z - __uint_as_float(hi.z));
            hi.w = to_tf32(v.w); lo.w = to_tf32(v.w - __uint_as_float(hi.w));
            *(uint4*)(smem + SM_AHI + r * TSTRIDE + c4 * 4) = hi;
            *(uint4*)(smem + SM_ALO + r * TSTRIDE + c4 * 4) = lo;
        }
    }
    __syncthreads();

    int warp = tid >> 5, lane = tid & 31;
    int grp = lane >> 2, qid = lane & 3;   // groupID / thread-in-group
    int r0 = warp * 16;

    float acc[16][4];
#pragma unroll
    for (int nt = 0; nt < 16; nt++)
#pragma unroll
        for (int c = 0; c < 4; c++) acc[nt][c] = 0.f;

    const uint32_t* sAhi = smem + SM_AHI;
    const uint32_t* sAlo = smem + SM_ALO;
    const uint32_t* sWt  = smem + SM_W;

#pragma unroll
    for (int ks = 0; ks < 16; ks++) {
        int kb = ks * 8;
        int arow = (r0 + grp) * TSTRIDE;
        uint32_t ah0 = sAhi[arow + kb + qid];
        uint32_t ah1 = sAhi[arow + 8 * TSTRIDE + kb + qid];
        uint32_t ah2 = sAhi[arow + kb + qid + 4];
        uint32_t ah3 = sAhi[arow + 8 * TSTRIDE + kb + qid + 4];
        uint32_t al0 = sAlo[arow + kb + qid];
        uint32_t al1 = sAlo[arow + 8 * TSTRIDE + kb + qid];
        uint32_t al2 = sAlo[arow + kb + qid + 4];
        uint32_t al3 = sAlo[arow + 8 * TSTRIDE + kb + qid + 4];
#pragma unroll
        for (int nt = 0; nt < 16; nt++) {
            uint32_t b0 = sWt[(kb + qid) * TSTRIDE + nt * 8 + grp];
            uint32_t b1 = sWt[(kb + qid + 4) * TSTRIDE + nt * 8 + grp];
            mma_tf32(acc[nt], ah0, ah1, ah2, ah3, b0, b1);
            mma_tf32(acc[nt], al0, al1, al2, al3, b0, b1);
        }
    }
    __syncthreads();  // A tiles dead; reuse as sO

    // LN + ReLU. Thread owns rows ra = r0+grp, rb = ra+8; cols nt*8 + 2*qid + {0,1}.
    float* sO = (float*)(smem + SM_AHI);
    {
        float sa = 0.f, qa = 0.f, sb = 0.f, qb = 0.f;
#pragma unroll
        for (int nt = 0; nt < 16; nt++) {
            int c0 = nt * 8 + 2 * qid;
            float t0 = acc[nt][0] + sBias[c0];
            float t1 = acc[nt][1] + sBias[c0 + 1];
            float t2 = acc[nt][2] + sBias[c0];
            float t3 = acc[nt][3] + sBias[c0 + 1];
            sa += t0 + t1; qa += t0 * t0 + t1 * t1;
            sb += t2 + t3; qb += t2 * t2 + t3 * t3;
        }
#pragma unroll
        for (int o = 1; o <= 2; o <<= 1) {
            sa += __shfl_xor_sync(0xffffffffu, sa, o);
            qa += __shfl_xor_sync(0xffffffffu, qa, o);
            sb += __shfl_xor_sync(0xffffffffu, sb, o);
            qb += __shfl_xor_sync(0xffffffffu, qb, o);
        }
        float mua = sa * (1.f / 128.f);
        float mub = sb * (1.f / 128.f);
        float ra_std = rsqrtf(fmaxf(qa * (1.f / 128.f) - mua * mua, 0.f) + LN_EPS);
        float rb_std = rsqrtf(fmaxf(qb * (1.f / 128.f) - mub * mub, 0.f) + LN_EPS);
        int ra = r0 + grp, rb = ra + 8;
#pragma unroll
        for (int nt = 0; nt < 16; nt++) {
            int c0 = nt * 8 + 2 * qid;
            float t0 = acc[nt][0] + sBias[c0] - mua;
            float t1 = acc[nt][1] + sBias[c0 + 1] - mua;
            float t2 = acc[nt][2] + sBias[c0] - mub;
            float t3 = acc[nt][3] + sBias[c0 + 1] - mub;
            sO[ra * TSTRIDE + c0]     = fmaxf(t0 * ra_std * sG[c0] + sBe[c0], 0.f);
            sO[ra * TSTRIDE + c0 + 1] = fmaxf(t1 * ra_std * sG[c0 + 1] + sBe[c0 + 1], 0.f);
            sO[rb * TSTRIDE + c0]     = fmaxf(t2 * rb_std * sG[c0] + sBe[c0], 0.f);
            sO[rb * TSTRIDE + c0 + 1] = fmaxf(t3 * rb_std * sG[c0 + 1] + sBe[c0 + 1], 0.f);
        }
    }
    __syncthreads();

    // coalesced store + residual
    for (int i = tid; i < 128 * 128; i += 256) {
        int r = i >> 7, c = i & 127;
        int node = rbase + r;
        if (node < N_NODES) {
            float o = sO[r * TSTRIDE + c];
            if (add_res) o += g_h[(size_t)node * HID + c];
            out[(size_t)node * HID + c] = o;
        }
    }
}

// ---------------- launch ----------------
extern "C" void kernel_launch(void* const* d_in, const int* in_sizes, int n_in,
                              void* d_out, int out_size) {
    const float* x   = (const float*)d_in[0];
    const void*  eix = d_in[1];
    const float* Win = (const float*)d_in[2];
    const float* bin = (const float*)d_in[3];
    const float* Wc  = (const float*)d_in[4];
    const float* bc  = (const float*)d_in[5];
    const float* lg  = (const float*)d_in[6];
    const float* lb  = (const float*)d_in[7];
    int E = in_sizes[1] / 2;

    static bool attr_set = false;  // idempotent attribute set
    if (!attr_set) {
        cudaFuncSetAttribute(k_transform_tc, cudaFuncAttributeMaxDynamicSharedMemorySize,
                             SM_U32_TOTAL * (int)sizeof(uint32_t));
        attr_set = true;
    }

    void* h_addr = nullptr;
    cudaGetSymbolAddress(&h_addr, g_h);

    k_detect<<<1, 256>>>((const unsigned int*)eix, 4096);
    k_zero<<<(N_NODES + 255) / 256, 256>>>();
    k_hist<<<(E + 255) / 256, 256>>>(eix, E);
    int nb = (N_NODES + SCAN_B - 1) / SCAN_B;
    k_scan1<<<nb, SCAN_B>>>();
    k_scan2<<<1, 256>>>(nb);
    k_scan3<<<nb, SCAN_B>>>();
    k_fill<<<(E + 255) / 256, 256>>>(eix, E);

    k_proj<<<(N_NODES + 7) / 8, 128>>>(x, Win, bin);

    int tiles = N_ROWS_PAD / 128;  // 782
    size_t tsmem = SM_U32_TOTAL * sizeof(uint32_t);  // ~198KB
    for (int l = 0; l < 3; l++) {
        k_gather<<<(N_NODES + 7) / 8, 256>>>();
        float* out = (l == 2) ? (float*)d_out : (float*)h_addr;
        k_transform_tc<<<tiles, 256, tsmem>>>(
            Wc + (size_t)l * HID * HID, bc + l * HID, lg + l * HID, lb + l * HID,
            out, (l > 0) ? 1 : 0);
    }
}

// round 6
// speedup vs baseline: 1.2156x; 1.2156x over previous
#include <cuda_runtime.h>
#include <cstdint>

#define N_NODES 100000
#define N_ROWS_PAD 100096              // 782 * 128
#define N_EDGES 1600000
#define HID     128
#define IN_DIM  16
#define LN_EPS  1e-5f
#define SCAN_B  512

// ---------------- device scratch ----------------
__device__ int   g_deg[N_NODES];
__device__ float g_dis[N_NODES];
__device__ int   g_off[N_NODES + 1];
__device__ int2  g_csr[N_EDGES];
__device__ float g_h[(size_t)N_NODES * HID];
__device__ float g_p[(size_t)N_ROWS_PAD * HID];   // padded, .bss zeros
__device__ int   g_bsum[256];
__device__ int   g_wide;

// ---------------- tf32 helpers (non-'a' ISA, sm_80+) ----------------
__device__ __forceinline__ uint32_t to_tf32(float v) {
    uint32_t b;
    asm("cvt.rna.tf32.f32 %0, %1;" : "=r"(b) : "f"(v));
    return b;
}
__device__ __forceinline__ void mma_tf32(float c[4], const uint32_t a[4],
                                         uint32_t b0, uint32_t b1) {
    asm("mma.sync.aligned.m16n8k8.row.col.f32.tf32.tf32.f32 "
        "{%0,%1,%2,%3}, {%4,%5,%6,%7}, {%8,%9}, {%0,%1,%2,%3};"
        : "+f"(c[0]), "+f"(c[1]), "+f"(c[2]), "+f"(c[3])
        : "r"(a[0]), "r"(a[1]), "r"(a[2]), "r"(a[3]), "r"(b0), "r"(b1));
}

// ---------------- edge dtype detection ----------------
__global__ void k_detect(const unsigned int* __restrict__ e32, int nwords) {
    __shared__ unsigned int s_or;
    if (threadIdx.x == 0) s_or = 0u;
    __syncthreads();
    unsigned int v = 0u;
    for (int i = threadIdx.x * 2 + 1; i < nwords; i += blockDim.x * 2) v |= e32[i];
    atomicOr(&s_or, v);
    __syncthreads();
    if (threadIdx.x == 0) g_wide = (s_or == 0u) ? 1 : 0;
}

__device__ __forceinline__ int load_edge(const void* eidx, long idx, int wide) {
    if (wide) return (int)((const long long*)eidx)[idx];
    return ((const int*)eidx)[idx];
}

// ---------------- CSR build ----------------
__global__ void k_zero() {
    int i = blockIdx.x * blockDim.x + threadIdx.x;
    if (i < N_NODES) g_deg[i] = 0;
}
__global__ void k_hist(const void* __restrict__ eidx, int E) {
    int i = blockIdx.x * blockDim.x + threadIdx.x;
    if (i >= E) return;
    atomicAdd(&g_deg[load_edge(eidx, (long)E + i, g_wide)], 1);
}
__global__ void k_scan1() {
    __shared__ int s[SCAN_B];
    int tid = threadIdx.x;
    int i = blockIdx.x * SCAN_B + tid;
    s[tid] = (i < N_NODES) ? g_deg[i] : 0;
    __syncthreads();
    for (int o = SCAN_B / 2; o > 0; o >>= 1) {
        if (tid < o) s[tid] += s[tid + o];
        __syncthreads();
    }
    if (tid == 0) g_bsum[blockIdx.x] = s[0];
}
__global__ void k_scan2(int nb) {
    __shared__ int s[256];
    int tid = threadIdx.x;
    int v = (tid < nb) ? g_bsum[tid] : 0;
    s[tid] = v;
    __syncthreads();
    for (int o = 1; o < 256; o <<= 1) {
        int t = (tid >= o) ? s[tid - o] : 0;
        __syncthreads();
        s[tid] += t;
        __syncthreads();
    }
    if (tid < nb) g_bsum[tid] = s[tid] - v;
}
__global__ void k_scan3() {
    __shared__ int s[SCAN_B];
    int tid = threadIdx.x;
    int i = blockIdx.x * SCAN_B + tid;
    int v = (i < N_NODES) ? g_deg[i] : 0;
    s[tid] = v;
    __syncthreads();
    for (int o = 1; o < SCAN_B; o <<= 1) {
        int t = (tid >= o) ? s[tid - o] : 0;
        __syncthreads();
        s[tid] += t;
        __syncthreads();
    }
    int off = g_bsum[blockIdx.x] + s[tid] - v;
    if (i < N_NODES) {
        g_off[i] = off;
        g_dis[i] = rsqrtf((float)(v + 1));
        if (i == N_NODES - 1) g_off[N_NODES] = off + v;
        g_deg[i] = off;
    }
}
__global__ void k_fill(const void* __restrict__ eidx, int E) {
    int i = blockIdx.x * blockDim.x + threadIdx.x;
    if (i >= E) return;
    int wide = g_wide;
    int sidx = load_edge(eidx, i, wide);
    int didx = load_edge(eidx, (long)E + i, wide);
    int pos = atomicAdd(&g_deg[didx], 1);
    g_csr[pos] = make_int2(sidx, __float_as_int(g_dis[sidx]));
}

// ---------------- input projection ----------------
__global__ void k_proj(const float* __restrict__ x, const float* __restrict__ Win,
                       const float* __restrict__ bin) {
    __shared__ float sW[IN_DIM * HID];
    __shared__ float sx[8 * IN_DIM];
    int tid = threadIdx.x;
    for (int i = tid; i < IN_DIM * HID; i += 128) sW[i] = Win[i];
    int base = blockIdx.x * 8;
    {
        int n = tid / IN_DIM, k = tid % IN_DIM;
        int node = base + n;
        sx[tid] = (node < N_NODES) ? x[(size_t)node * IN_DIM + k] : 0.f;
    }
    __syncthreads();
    float bc = bin[tid];
    for (int n = 0; n < 8; n++) {
        int node = base + n;
        if (node >= N_NODES) break;
        float sum = bc;
#pragma unroll
        for (int k = 0; k < IN_DIM; k++) sum += sx[n * IN_DIM + k] * sW[k * HID + tid];
        g_h[(size_t)node * HID + tid] = sum;
    }
}

// ---------------- propagate (MLP=4 gather) ----------------
__global__ void k_gather() {
    int warp = threadIdx.x >> 5, lane = threadIdx.x & 31;
    int d = blockIdx.x * 8 + warp;
    if (d >= N_NODES) return;
    int start = g_off[d], end = g_off[d + 1];
    float dd = g_dis[d];
    const float4* hv = (const float4*)g_h;
    float4 acc = hv[(size_t)d * 32 + lane];
    acc.x *= dd; acc.y *= dd; acc.z *= dd; acc.w *= dd;
    for (int j = start; j < end; j += 32) {
        int2 ew = make_int2(0, 0);
        if (j + lane < end) ew = g_csr[j + lane];
        int cnt = min(32, end - j);
        int t = 0;
        for (; t + 4 <= cnt; t += 4) {
            int s0 = __shfl_sync(0xffffffffu, ew.x, t);
            int s1 = __shfl_sync(0xffffffffu, ew.x, t + 1);
            int s2 = __shfl_sync(0xffffffffu, ew.x, t + 2);
            int s3 = __shfl_sync(0xffffffffu, ew.x, t + 3);
            float w0 = __int_as_float(__shfl_sync(0xffffffffu, ew.y, t));
            float w1 = __int_as_float(__shfl_sync(0xffffffffu, ew.y, t + 1));
            float w2 = __int_as_float(__shfl_sync(0xffffffffu, ew.y, t + 2));
            float w3 = __int_as_float(__shfl_sync(0xffffffffu, ew.y, t + 3));
            float4 v0 = hv[(size_t)s0 * 32 + lane];
            float4 v1 = hv[(size_t)s1 * 32 + lane];
            float4 v2 = hv[(size_t)s2 * 32 + lane];
            float4 v3 = hv[(size_t)s3 * 32 + lane];
            acc.x += w0 * v0.x; acc.y += w0 * v0.y; acc.z += w0 * v0.z; acc.w += w0 * v0.w;
            acc.x += w1 * v1.x; acc.y += w1 * v1.y; acc.z += w1 * v1.z; acc.w += w1 * v1.w;
            acc.x += w2 * v2.x; acc.y += w2 * v2.y; acc.z += w2 * v2.z; acc.w += w2 * v2.w;
            acc.x += w3 * v3.x; acc.y += w3 * v3.y; acc.z += w3 * v3.z; acc.w += w3 * v3.w;
        }
        for (; t < cnt; t++) {
            int   s = __shfl_sync(0xffffffffu, ew.x, t);
            float w = __int_as_float(__shfl_sync(0xffffffffu, ew.y, t));
            float4 v = hv[(size_t)s * 32 + lane];
            acc.x += w * v.x; acc.y += w * v.y; acc.z += w * v.z; acc.w += w * v.w;
        }
    }
    acc.x *= dd; acc.y *= dd; acc.z *= dd; acc.w *= dd;
    ((float4*)g_p)[(size_t)d * 32 + lane] = acc;
}

// ---------------- transform via mma.sync tf32, 4x2 warp grid ----------------
// Block: 128-row tile, 256 threads = 8 warps laid out 4(rows) x 2(cols).
// Warp (wr, wc) owns rows [32*wr, 32*wr+32) x cols [64*wc, 64*wc+64).
// smem (dynamic u32):
//   sAhi [128 x 132]  tf32(p)
//   sAlo [128 x 132]  tf32(p - tf32(p))
//   sW   [128 x 136]  tf32(W) [k][n]  (stride 136 -> conflict-free B frags)
#define ASTRIDE 132
#define WSTRIDE 136
#define SM_AHI 0
#define SM_ALO (128 * ASTRIDE)
#define SM_W   (256 * ASTRIDE)
#define SM_U32_TOTAL (256 * ASTRIDE + 128 * WSTRIDE)

__global__ void __launch_bounds__(256) k_transform_tc(
        const float* __restrict__ W, const float* __restrict__ bias,
        const float* __restrict__ gamma, const float* __restrict__ beta,
        float* __restrict__ out, int add_res) {
    extern __shared__ uint32_t smem[];
    __shared__ float sBias[HID], sG[HID], sBe[HID];
    __shared__ float psum[2][128], psq[2][128];
    int tid = threadIdx.x;
    int rbase = blockIdx.x * 128;

    for (int i = tid; i < HID; i += 256) {
        sBias[i] = bias[i];
        sG[i] = gamma[i];
        sBe[i] = beta[i];
    }
    // stage W: [k][n] -> sW[k*136+n], tf32
    for (int i = tid; i < HID * HID; i += 256) {
        int k = i >> 7, n = i & 127;
        smem[SM_W + k * WSTRIDE + n] = to_tf32(W[i]);
    }
    // stage A hi/lo from g_p
    {
        const float4* p4 = (const float4*)g_p;
        for (int i = tid; i < 128 * 32; i += 256) {
            int r = i >> 5, c4 = i & 31;
            float4 v = p4[(size_t)(rbase + r) * 32 + c4];
            uint4 hi, lo;
            hi.x = to_tf32(v.x); lo.x = to_tf32(v.x - __uint_as_float(hi.x));
            hi.y = to_tf32(v.y); lo.y = to_tf32(v.y - __uint_as_float(hi.y));
            hi.z = to_tf32(v.z); lo.z = to_tf32(v.z - __uint_as_float(hi.z));
            hi.w = to_tf32(v.w); lo.w = to_tf32(v.w - __uint_as_float(hi.w));
            *(uint4*)(smem + SM_AHI + r * ASTRIDE + c4 * 4) = hi;
            *(uint4*)(smem + SM_ALO + r * ASTRIDE + c4 * 4) = lo;
        }
    }
    __syncthreads();

    int warp = tid >> 5, lane = tid & 31;
    int grp = lane >> 2, qid = lane & 3;
    int wr = warp >> 1, wc = warp & 1;
    int row0 = wr * 32;
    int col0 = wc * 64;

    float acc[2][8][4];
#pragma unroll
    for (int m = 0; m < 2; m++)
#pragma unroll
        for (int n = 0; n < 8; n++)
#pragma unroll
            for (int c = 0; c < 4; c++) acc[m][n][c] = 0.f;

    const uint32_t* sAhi = smem + SM_AHI;
    const uint32_t* sAlo = smem + SM_ALO;
    const uint32_t* sWt  = smem + SM_W;

#pragma unroll 2
    for (int ks = 0; ks < 16; ks++) {
        int kb = ks * 8;
        uint32_t ah[2][4], al[2][4];
#pragma unroll
        for (int m = 0; m < 2; m++) {
            int ra = (row0 + m * 16 + grp) * ASTRIDE + kb + qid;
            ah[m][0] = sAhi[ra];
            ah[m][1] = sAhi[ra + 8 * ASTRIDE];
            ah[m][2] = sAhi[ra + 4];
            ah[m][3] = sAhi[ra + 8 * ASTRIDE + 4];
            al[m][0] = sAlo[ra];
            al[m][1] = sAlo[ra + 8 * ASTRIDE];
            al[m][2] = sAlo[ra + 4];
            al[m][3] = sAlo[ra + 8 * ASTRIDE + 4];
        }
#pragma unroll
        for (int n = 0; n < 8; n++) {
            int ba = (kb + qid) * WSTRIDE + col0 + n * 8 + grp;
            uint32_t b0 = sWt[ba];
            uint32_t b1 = sWt[ba + 4 * WSTRIDE];
            mma_tf32(acc[0][n], ah[0], b0, b1);
            mma_tf32(acc[0][n], al[0], b0, b1);
            mma_tf32(acc[1][n], ah[1], b0, b1);
            mma_tf32(acc[1][n], al[1], b0, b1);
        }
    }

    // bias add + per-row partial sums over this warp's 64 cols
    float s[4] = {0.f, 0.f, 0.f, 0.f}, q[4] = {0.f, 0.f, 0.f, 0.f};
#pragma unroll
    for (int m = 0; m < 2; m++)
#pragma unroll
        for (int n = 0; n < 8; n++) {
            int c0 = col0 + n * 8 + 2 * qid;
            float b0 = sBias[c0], b1 = sBias[c0 + 1];
            acc[m][n][0] += b0; acc[m][n][1] += b1;
            acc[m][n][2] += b0; acc[m][n][3] += b1;
            s[m * 2]     += acc[m][n][0] + acc[m][n][1];
            q[m * 2]     += acc[m][n][0] * acc[m][n][0] + acc[m][n][1] * acc[m][n][1];
            s[m * 2 + 1] += acc[m][n][2] + acc[m][n][3];
            q[m * 2 + 1] += acc[m][n][2] * acc[m][n][2] + acc[m][n][3] * acc[m][n][3];
        }
#pragma unroll
    for (int o = 1; o <= 2; o <<= 1)
#pragma unroll
        for (int i = 0; i < 4; i++) {
            s[i] += __shfl_xor_sync(0xffffffffu, s[i], o);
            q[i] += __shfl_xor_sync(0xffffffffu, q[i], o);
        }
    if (qid == 0) {
#pragma unroll
        for (int i = 0; i < 4; i++) {
            int r = row0 + (i >> 1) * 16 + grp + (i & 1) * 8;
            psum[wc][r] = s[i];
            psq[wc][r] = q[i];
        }
    }
    __syncthreads();

    float mu[4], rstd[4];
#pragma unroll
    for (int i = 0; i < 4; i++) {
        int r = row0 + (i >> 1) * 16 + grp + (i & 1) * 8;
        float tot = psum[0][r] + psum[1][r];
        float tq  = psq[0][r] + psq[1][r];
        mu[i] = tot * (1.f / 128.f);
        rstd[i] = rsqrtf(fmaxf(tq * (1.f / 128.f) - mu[i] * mu[i], 0.f) + LN_EPS);
    }

    // LN + ReLU + residual + store (float2, 32B-contiguous per quad)
#pragma unroll
    for (int m = 0; m < 2; m++) {
        int ra = row0 + m * 16 + grp;
        int rb = ra + 8;
        int na = rbase + ra, nb2 = rbase + rb;
#pragma unroll
        for (int n = 0; n < 8; n++) {
            int c0 = col0 + n * 8 + 2 * qid;
            float g0 = sG[c0], g1 = sG[c0 + 1], e0 = sBe[c0], e1 = sBe[c0 + 1];
            if (na < N_NODES) {
                float2 o;
                o.x = fmaxf((acc[m][n][0] - mu[m * 2]) * rstd[m * 2] * g0 + e0, 0.f);
                o.y = fmaxf((acc[m][n][1] - mu[m * 2]) * rstd[m * 2] * g1 + e1, 0.f);
                if (add_res) {
                    float2 hp = *(const float2*)(g_h + (size_t)na * HID + c0);
                    o.x += hp.x; o.y += hp.y;
                }
                *(float2*)(out + (size_t)na * HID + c0) = o;
            }
            if (nb2 < N_NODES) {
                float2 o;
                o.x = fmaxf((acc[m][n][2] - mu[m * 2 + 1]) * rstd[m * 2 + 1] * g0 + e0, 0.f);
                o.y = fmaxf((acc[m][n][3] - mu[m * 2 + 1]) * rstd[m * 2 + 1] * g1 + e1, 0.f);
                if (add_res) {
                    float2 hp = *(const float2*)(g_h + (size_t)nb2 * HID + c0);
                    o.x += hp.x; o.y += hp.y;
                }
                *(float2*)(out + (size_t)nb2 * HID + c0) = o;
            }
        }
    }
}

// ---------------- launch ----------------
extern "C" void kernel_launch(void* const* d_in, const int* in_sizes, int n_in,
                              void* d_out, int out_size) {
    const float* x   = (const float*)d_in[0];
    const void*  eix = d_in[1];
    const float* Win = (const float*)d_in[2];
    const float* bin = (const float*)d_in[3];
    const float* Wc  = (const float*)d_in[4];
    const float* bc  = (const float*)d_in[5];
    const float* lg  = (const float*)d_in[6];
    const float* lb  = (const float*)d_in[7];
    int E = in_sizes[1] / 2;

    static bool attr_set = false;  // idempotent attribute set
    if (!attr_set) {
        cudaFuncSetAttribute(k_transform_tc, cudaFuncAttributeMaxDynamicSharedMemorySize,
                             SM_U32_TOTAL * (int)sizeof(uint32_t));
        attr_set = true;
    }

    void* h_addr = nullptr;
    cudaGetSymbolAddress(&h_addr, g_h);

    k_detect<<<1, 256>>>((const unsigned int*)eix, 4096);
    k_zero<<<(N_NODES + 255) / 256, 256>>>();
    k_hist<<<(E + 255) / 256, 256>>>(eix, E);
    int nb = (N_NODES + SCAN_B - 1) / SCAN_B;
    k_scan1<<<nb, SCAN_B>>>();
    k_scan2<<<1, 256>>>(nb);
    k_scan3<<<nb, SCAN_B>>>();
    k_fill<<<(E + 255) / 256, 256>>>(eix, E);

    k_proj<<<(N_NODES + 7) / 8, 128>>>(x, Win, bin);

    int tiles = N_ROWS_PAD / 128;  // 782
    size_t tsmem = SM_U32_TOTAL * sizeof(uint32_t);  // ~205KB
    for (int l = 0; l < 3; l++) {
        k_gather<<<(N_NODES + 7) / 8, 256>>>();
        float* out = (l == 2) ? (float*)d_out : (float*)h_addr;
        k_transform_tc<<<tiles, 256, tsmem>>>(
            Wc + (size_t)l * HID * HID, bc + l * HID, lg + l * HID, lb + l * HID,
            out, (l > 0) ? 1 : 0);
    }
}

// round 7
// speedup vs baseline: 1.2763x; 1.0499x over previous
#include <cuda_runtime.h>
#include <cstdint>

#define N_NODES 100000
#define N_ROWS_PAD 100096              // 1564 * 64
#define N_EDGES 1600000
#define HID     128
#define IN_DIM  16
#define LN_EPS  1e-5f
#define SCAN_B  512

typedef unsigned long long ull;

// ---------------- device scratch ----------------
__device__ int   g_deg[N_NODES];
__device__ float g_dis[N_NODES];
__device__ int   g_off[N_NODES + 1];
__device__ int2  g_csr[N_EDGES];
__device__ float g_h[(size_t)N_NODES * HID];
__device__ float g_p[(size_t)N_ROWS_PAD * HID];   // padded, .bss zeros
__device__ int   g_bsum[256];
__device__ int   g_wide;

// ---------------- packed f32x2 helpers ----------------
__device__ __forceinline__ void fma2(ull& d, ull a, ull b) {
    asm("fma.rn.f32x2 %0, %1, %2, %0;" : "+l"(d) : "l"(a), "l"(b));
}
__device__ __forceinline__ float2 unpack2(ull v) {
    float2 f;
    asm("mov.b64 {%0,%1}, %2;" : "=f"(f.x), "=f"(f.y) : "l"(v));
    return f;
}
__device__ __forceinline__ ull pack2(float lo, float hi) {
    ull v;
    asm("mov.b64 %0, {%1,%2};" : "=l"(v) : "f"(lo), "f"(hi));
    return v;
}

// ---------------- zero + edge dtype detection (merged) ----------------
__global__ void k_zero_detect(const unsigned int* __restrict__ e32, int nwords) {
    int i = blockIdx.x * blockDim.x + threadIdx.x;
    if (i < N_NODES) g_deg[i] = 0;
    if (blockIdx.x == 0) {
        __shared__ unsigned int s_or;
        if (threadIdx.x == 0) s_or = 0u;
        __syncthreads();
        unsigned int v = 0u;
        for (int j = threadIdx.x * 2 + 1; j < nwords; j += blockDim.x * 2) v |= e32[j];
        atomicOr(&s_or, v);
        __syncthreads();
        if (threadIdx.x == 0) g_wide = (s_or == 0u) ? 1 : 0;
    }
}

__device__ __forceinline__ int load_edge(const void* eidx, long idx, int wide) {
    if (wide) return (int)((const long long*)eidx)[idx];
    return ((const int*)eidx)[idx];
}

// ---------------- CSR build ----------------
__global__ void k_hist(const void* __restrict__ eidx, int E) {
    int i = blockIdx.x * blockDim.x + threadIdx.x;
    if (i >= E) return;
    atomicAdd(&g_deg[load_edge(eidx, (long)E + i, g_wide)], 1);
}
__global__ void k_scan1() {
    __shared__ int s[SCAN_B];
    int tid = threadIdx.x;
    int i = blockIdx.x * SCAN_B + tid;
    s[tid] = (i < N_NODES) ? g_deg[i] : 0;
    __syncthreads();
    for (int o = SCAN_B / 2; o > 0; o >>= 1) {
        if (tid < o) s[tid] += s[tid + o];
        __syncthreads();
    }
    if (tid == 0) g_bsum[blockIdx.x] = s[0];
}
__global__ void k_scan2(int nb) {
    __shared__ int s[256];
    int tid = threadIdx.x;
    int v = (tid < nb) ? g_bsum[tid] : 0;
    s[tid] = v;
    __syncthreads();
    for (int o = 1; o < 256; o <<= 1) {
        int t = (tid >= o) ? s[tid - o] : 0;
        __syncthreads();
        s[tid] += t;
        __syncthreads();
    }
    if (tid < nb) g_bsum[tid] = s[tid] - v;
}
__global__ void k_scan3() {
    __shared__ int s[SCAN_B];
    int tid = threadIdx.x;
    int i = blockIdx.x * SCAN_B + tid;
    int v = (i < N_NODES) ? g_deg[i] : 0;
    s[tid] = v;
    __syncthreads();
    for (int o = 1; o < SCAN_B; o <<= 1) {
        int t = (tid >= o) ? s[tid - o] : 0;
        __syncthreads();
        s[tid] += t;
        __syncthreads();
    }
    int off = g_bsum[blockIdx.x] + s[tid] - v;
    if (i < N_NODES) {
        g_off[i] = off;
        g_dis[i] = rsqrtf((float)(v + 1));
        if (i == N_NODES - 1) g_off[N_NODES] = off + v;
        g_deg[i] = off;
    }
}
__global__ void k_fill(const void* __restrict__ eidx, int E) {
    int i = blockIdx.x * blockDim.x + threadIdx.x;
    if (i >= E) return;
    int wide = g_wide;
    int sidx = load_edge(eidx, i, wide);
    int didx = load_edge(eidx, (long)E + i, wide);
    int pos = atomicAdd(&g_deg[didx], 1);
    g_csr[pos] = make_int2(sidx, __float_as_int(g_dis[sidx]));
}

// ---------------- input projection ----------------
__global__ void k_proj(const float* __restrict__ x, const float* __restrict__ Win,
                       const float* __restrict__ bin) {
    __shared__ float sW[IN_DIM * HID];
    __shared__ float sx[8 * IN_DIM];
    int tid = threadIdx.x;
    for (int i = tid; i < IN_DIM * HID; i += 128) sW[i] = Win[i];
    int base = blockIdx.x * 8;
    {
        int n = tid / IN_DIM, k = tid % IN_DIM;
        int node = base + n;
        sx[tid] = (node < N_NODES) ? x[(size_t)node * IN_DIM + k] : 0.f;
    }
    __syncthreads();
    float bc = bin[tid];
    for (int n = 0; n < 8; n++) {
        int node = base + n;
        if (node >= N_NODES) break;
        float sum = bc;
#pragma unroll
        for (int k = 0; k < IN_DIM; k++) sum += sx[n * IN_DIM + k] * sW[k * HID + tid];
        g_h[(size_t)node * HID + tid] = sum;
    }
}

// ---------------- propagate (MLP=4 gather) ----------------
__global__ void k_gather() {
    int warp = threadIdx.x >> 5, lane = threadIdx.x & 31;
    int d = blockIdx.x * 8 + warp;
    if (d >= N_NODES) return;
    int start = g_off[d], end = g_off[d + 1];
    float dd = g_dis[d];
    const float4* hv = (const float4*)g_h;
    float4 acc = hv[(size_t)d * 32 + lane];
    acc.x *= dd; acc.y *= dd; acc.z *= dd; acc.w *= dd;
    for (int j = start; j < end; j += 32) {
        int2 ew = make_int2(0, 0);
        if (j + lane < end) ew = g_csr[j + lane];
        int cnt = min(32, end - j);
        int t = 0;
        for (; t + 4 <= cnt; t += 4) {
            int s0 = __shfl_sync(0xffffffffu, ew.x, t);
            int s1 = __shfl_sync(0xffffffffu, ew.x, t + 1);
            int s2 = __shfl_sync(0xffffffffu, ew.x, t + 2);
            int s3 = __shfl_sync(0xffffffffu, ew.x, t + 3);
            float w0 = __int_as_float(__shfl_sync(0xffffffffu, ew.y, t));
            float w1 = __int_as_float(__shfl_sync(0xffffffffu, ew.y, t + 1));
            float w2 = __int_as_float(__shfl_sync(0xffffffffu, ew.y, t + 2));
            float w3 = __int_as_float(__shfl_sync(0xffffffffu, ew.y, t + 3));
            float4 v0 = hv[(size_t)s0 * 32 + lane];
            float4 v1 = hv[(size_t)s1 * 32 + lane];
            float4 v2 = hv[(size_t)s2 * 32 + lane];
            float4 v3 = hv[(size_t)s3 * 32 + lane];
            acc.x += w0 * v0.x; acc.y += w0 * v0.y; acc.z += w0 * v0.z; acc.w += w0 * v0.w;
            acc.x += w1 * v1.x; acc.y += w1 * v1.y; acc.z += w1 * v1.z; acc.w += w1 * v1.w;
            acc.x += w2 * v2.x; acc.y += w2 * v2.y; acc.z += w2 * v2.z; acc.w += w2 * v2.w;
            acc.x += w3 * v3.x; acc.y += w3 * v3.y; acc.z += w3 * v3.z; acc.w += w3 * v3.w;
        }
        for (; t < cnt; t++) {
            int   s = __shfl_sync(0xffffffffu, ew.x, t);
            float w = __int_as_float(__shfl_sync(0xffffffffu, ew.y, t));
            float4 v = hv[(size_t)s * 32 + lane];
            acc.x += w * v.x; acc.y += w * v.y; acc.z += w * v.z; acc.w += w * v.w;
        }
    }
    acc.x *= dd; acc.y *= dd; acc.z *= dd; acc.w *= dd;
    ((float4*)g_p)[(size_t)d * 32 + lane] = acc;
}

// ---------------- transform: f32x2 GEMM, warp = 16 rows x 64 cols ----------------
// Block: 64-row tile, 256 threads = 8 warps (4 row-groups x 2 col-groups).
// Warp (wr, wc): rows [16wr,16wr+16), cols [64wc,64wc+64); lane owns cols
// (64wc+2*lane, +1) -> W fetch = one contiguous 16B LDS.128 per lane per k-pair.
// smem: sW2 [64 k-pairs][128 cols] ull (64KB) + sP [64][128] f32 (32KB).
// sP reused as LN partial-sum staging after the mainloop.
#define SM_W_ULL   0
#define SM_P_F32   (64 * 128 * 2)      // in f32 units: sW2 is 64*128 ull = 16384 f32*2
#define SM_F32_TOTAL (64 * 128 * 2 + 64 * 128)

__global__ void __launch_bounds__(256, 2) k_transform(
        const float* __restrict__ W, const float* __restrict__ bias,
        const float* __restrict__ gamma, const float* __restrict__ beta,
        float* __restrict__ out, int add_res) {
    extern __shared__ float smemf[];
    ull*   sW2 = (ull*)smemf;                  // [t][c], t=k-pair 0..63, c 0..127
    float* sP  = smemf + SM_P_F32;             // [r][k], stride 128
    __shared__ float sBias[HID], sG[HID], sBe[HID];
    __shared__ float sMu[64], sRs[64];
    int tid = threadIdx.x;
    int rbase = blockIdx.x * 64;

    for (int i = tid; i < HID; i += 256) {
        sBias[i] = bias[i];
        sG[i] = gamma[i];
        sBe[i] = beta[i];
    }
    // stage W pairs: sW2[t*128+c] = (W[2t][c], W[2t+1][c])
    for (int i = tid; i < 64 * HID; i += 256) {
        int t = i >> 7, c = i & 127;
        sW2[t * 128 + c] = pack2(W[(2 * t) * HID + c], W[(2 * t + 1) * HID + c]);
    }
    // stage p tile rows
    {
        const float4* p4 = (const float4*)g_p;
        float4* sP4 = (float4*)sP;
        for (int i = tid; i < 64 * 32; i += 256)
            sP4[i] = p4[(size_t)rbase * 32 + i];
    }
    __syncthreads();

    int warp = tid >> 5, lane = tid & 31;
    int wr = warp >> 1, wc = warp & 1;
    int r0 = wr * 16;
    int c0 = wc * 64 + 2 * lane;   // this lane's two columns: c0, c0+1

    ull acc[16][2];
#pragma unroll
    for (int r = 0; r < 16; r++) { acc[r][0] = 0ull; acc[r][1] = 0ull; }

    const ulonglong2* sWv = (const ulonglong2*)(sW2);  // index (t*128 + c0)/2

#pragma unroll 2
    for (int t2 = 0; t2 < 32; t2++) {
        // W pairs for t = 2*t2 and 2*t2+1, this lane's 2 cols (contiguous 16B)
        ulonglong2 wA = sWv[((2 * t2) * 128 + c0) >> 1];
        ulonglong2 wB = sWv[((2 * t2 + 1) * 128 + c0) >> 1];
#pragma unroll
        for (int r = 0; r < 16; r++) {
            ulonglong2 pv = *(const ulonglong2*)(sP + (r0 + r) * 128 + 4 * t2);
            fma2(acc[r][0], pv.x, wA.x);
            fma2(acc[r][1], pv.x, wA.y);
            fma2(acc[r][0], pv.y, wB.x);
            fma2(acc[r][1], pv.y, wB.y);
        }
    }

    // unpack + bias; per-row partials
    float a[16][2];
    float b0 = sBias[c0], b1 = sBias[c0 + 1];
#pragma unroll
    for (int r = 0; r < 16; r++) {
        float2 e0 = unpack2(acc[r][0]);
        float2 e1 = unpack2(acc[r][1]);
        a[r][0] = e0.x + e0.y + b0;
        a[r][1] = e1.x + e1.y + b1;
    }

    __syncthreads();  // sP reads done everywhere; reuse as staging
    float* ps = sP;               // [64 rows][64 lanes]
    float* pq = sP + 64 * 64;     // [64 rows][64 lanes]
#pragma unroll
    for (int r = 0; r < 16; r++) {
        ps[(r0 + r) * 64 + wc * 32 + lane] = a[r][0] + a[r][1];
        pq[(r0 + r) * 64 + wc * 32 + lane] = a[r][0] * a[r][0] + a[r][1] * a[r][1];
    }
    __syncthreads();
    if (tid < 64) {
        const float4* s4 = (const float4*)(ps + tid * 64);
        const float4* q4 = (const float4*)(pq + tid * 64);
        float s = 0.f, q = 0.f;
#pragma unroll
        for (int i = 0; i < 16; i++) {
            float4 v = s4[i], w4 = q4[i];
            s += v.x + v.y + v.z + v.w;
            q += w4.x + w4.y + w4.z + w4.w;
        }
        float mu = s * (1.f / 128.f);
        sMu[tid] = mu;
        sRs[tid] = rsqrtf(fmaxf(q * (1.f / 128.f) - mu * mu, 0.f) + LN_EPS);
    }
    __syncthreads();

    float g0 = sG[c0], g1 = sG[c0 + 1], e0 = sBe[c0], e1 = sBe[c0 + 1];
#pragma unroll
    for (int r = 0; r < 16; r++) {
        int row = r0 + r;
        int node = rbase + row;
        if (node >= N_NODES) continue;
        float mu = sMu[row], rs = sRs[row];
        float2 o;
        o.x = fmaxf((a[r][0] - mu) * rs * g0 + e0, 0.f);
        o.y = fmaxf((a[r][1] - mu) * rs * g1 + e1, 0.f);
        if (add_res) {
            float2 hp = *(const float2*)(g_h + (size_t)node * HID + c0);
            o.x += hp.x; o.y += hp.y;
        }
        *(float2*)(out + (size_t)node * HID + c0) = o;
    }
}

// ---------------- launch ----------------
extern "C" void kernel_launch(void* const* d_in, const int* in_sizes, int n_in,
                              void* d_out, int out_size) {
    const float* x   = (const float*)d_in[0];
    const void*  eix = d_in[1];
    const float* Win = (const float*)d_in[2];
    const float* bin = (const float*)d_in[3];
    const float* Wc  = (const float*)d_in[4];
    const float* bc  = (const float*)d_in[5];
    const float* lg  = (const float*)d_in[6];
    const float* lb  = (const float*)d_in[7];
    int E = in_sizes[1] / 2;

    static bool attr_set = false;  // idempotent attribute set
    if (!attr_set) {
        cudaFuncSetAttribute(k_transform, cudaFuncAttributeMaxDynamicSharedMemorySize,
                             SM_F32_TOTAL * (int)sizeof(float));
        attr_set = true;
    }

    void* h_addr = nullptr;
    cudaGetSymbolAddress(&h_addr, g_h);

    k_zero_detect<<<(N_NODES + 255) / 256, 256>>>((const unsigned int*)eix, 4096);
    k_hist<<<(E + 255) / 256, 256>>>(eix, E);
    int nb = (N_NODES + SCAN_B - 1) / SCAN_B;
    k_scan1<<<nb, SCAN_B>>>();
    k_scan2<<<1, 256>>>(nb);
    k_scan3<<<nb, SCAN_B>>>();
    k_fill<<<(E + 255) / 256, 256>>>(eix, E);

    k_proj<<<(N_NODES + 7) / 8, 128>>>(x, Win, bin);

    int tiles = N_ROWS_PAD / 64;  // 1564
    size_t tsmem = SM_F32_TOTAL * sizeof(float);  // 96KB
    for (int l = 0; l < 3; l++) {
        k_gather<<<(N_NODES + 7) / 8, 256>>>();
        float* out = (l == 2) ? (float*)d_out : (float*)h_addr;
        k_transform<<<tiles, 256, tsmem>>>(
            Wc + (size_t)l * HID * HID, bc + l * HID, lg + l * HID, lb + l * HID,
            out, (l > 0) ? 1 : 0);
    }
}

// round 9
// speedup vs baseline: 1.3663x; 1.0705x over previous
#include <cuda_runtime.h>
#include <cuda_bf16.h>
#include <cstdint>

#define N_NODES 100000
#define N_ROWS_PAD 100096              // 782 * 128
#define N_EDGES 1600000
#define HID     128
#define IN_DIM  16
#define LN_EPS  1e-5f
#define SCAN_B  512

typedef unsigned long long ull;

// ---------------- device scratch ----------------
__device__ int   g_deg[N_NODES];
__device__ float g_dis[N_NODES];
__device__ int   g_off[N_NODES + 1];
__device__ int2  g_csr[N_EDGES];
__device__ float g_h[(size_t)N_NODES * HID];
__device__ float g_p[(size_t)N_ROWS_PAD * HID];   // padded, .bss zeros
__device__ int   g_bsum[256];
__device__ int   g_wide;

// ---------------- bf16 split helpers ----------------
__device__ __forceinline__ void split_bf16(float x, uint16_t& hi, uint16_t& lo) {
    __nv_bfloat16 h = __float2bfloat16(x);
    float r = x - __bfloat162float(h);
    __nv_bfloat16 l = __float2bfloat16(r);
    hi = __bfloat16_as_ushort(h);
    lo = __bfloat16_as_ushort(l);
}
__device__ __forceinline__ void mma_bf16(float c[4], const uint32_t a[4],
                                         uint32_t b0, uint32_t b1) {
    asm("mma.sync.aligned.m16n8k16.row.col.f32.bf16.bf16.f32 "
        "{%0,%1,%2,%3}, {%4,%5,%6,%7}, {%8,%9}, {%0,%1,%2,%3};"
        : "+f"(c[0]), "+f"(c[1]), "+f"(c[2]), "+f"(c[3])
        : "r"(a[0]), "r"(a[1]), "r"(a[2]), "r"(a[3]), "r"(b0), "r"(b1));
}

// ---------------- zero + edge dtype detection (merged) ----------------
__global__ void k_zero_detect(const unsigned int* __restrict__ e32, int nwords) {
    int i = blockIdx.x * blockDim.x + threadIdx.x;
    if (i < N_NODES) g_deg[i] = 0;
    if (blockIdx.x == 0) {
        __shared__ unsigned int s_or;
        if (threadIdx.x == 0) s_or = 0u;
        __syncthreads();
        unsigned int v = 0u;
        for (int j = threadIdx.x * 2 + 1; j < nwords; j += blockDim.x * 2) v |= e32[j];
        atomicOr(&s_or, v);
        __syncthreads();
        if (threadIdx.x == 0) g_wide = (s_or == 0u) ? 1 : 0;
    }
}

__device__ __forceinline__ int load_edge(const void* eidx, long idx, int wide) {
    if (wide) return (int)((const long long*)eidx)[idx];
    return ((const int*)eidx)[idx];
}

// ---------------- CSR build ----------------
__global__ void k_hist(const void* __restrict__ eidx, int E) {
    int i = blockIdx.x * blockDim.x + threadIdx.x;
    if (i >= E) return;
    atomicAdd(&g_deg[load_edge(eidx, (long)E + i, g_wide)], 1);
}
__global__ void k_scan1() {
    __shared__ int s[SCAN_B];
    int tid = threadIdx.x;
    int i = blockIdx.x * SCAN_B + tid;
    s[tid] = (i < N_NODES) ? g_deg[i] : 0;
    __syncthreads();
    for (int o = SCAN_B / 2; o > 0; o >>= 1) {
        if (tid < o) s[tid] += s[tid + o];
        __syncthreads();
    }
    if (tid == 0) g_bsum[blockIdx.x] = s[0];
}
__global__ void k_scan2(int nb) {
    __shared__ int s[256];
    int tid = threadIdx.x;
    int v = (tid < nb) ? g_bsum[tid] : 0;
    s[tid] = v;
    __syncthreads();
    for (int o = 1; o < 256; o <<= 1) {
        int t = (tid >= o) ? s[tid - o] : 0;
        __syncthreads();
        s[tid] += t;
        __syncthreads();
    }
    if (tid < nb) g_bsum[tid] = s[tid] - v;
}
__global__ void k_scan3() {
    __shared__ int s[SCAN_B];
    int tid = threadIdx.x;
    int i = blockIdx.x * SCAN_B + tid;
    int v = (i < N_NODES) ? g_deg[i] : 0;
    s[tid] = v;
    __syncthreads();
    for (int o = 1; o < SCAN_B; o <<= 1) {
        int t = (tid >= o) ? s[tid - o] : 0;
        __syncthreads();
        s[tid] += t;
        __syncthreads();
    }
    int off = g_bsum[blockIdx.x] + s[tid] - v;
    if (i < N_NODES) {
        g_off[i] = off;
        g_dis[i] = rsqrtf((float)(v + 1));
        if (i == N_NODES - 1) g_off[N_NODES] = off + v;
        g_deg[i] = off;
    }
}
__global__ void k_fill(const void* __restrict__ eidx, int E) {
    int i = blockIdx.x * blockDim.x + threadIdx.x;
    if (i >= E) return;
    int wide = g_wide;
    int sidx = load_edge(eidx, i, wide);
    int didx = load_edge(eidx, (long)E + i, wide);
    int pos = atomicAdd(&g_deg[didx], 1);
    g_csr[pos] = make_int2(sidx, __float_as_int(g_dis[sidx]));
}

// ---------------- input projection ----------------
__global__ void k_proj(const float* __restrict__ x, const float* __restrict__ Win,
                       const float* __restrict__ bin) {
    __shared__ float sW[IN_DIM * HID];
    __shared__ float sx[8 * IN_DIM];
    int tid = threadIdx.x;
    for (int i = tid; i < IN_DIM * HID; i += 128) sW[i] = Win[i];
    int base = blockIdx.x * 8;
    {
        int n = tid / IN_DIM, k = tid % IN_DIM;
        int node = base + n;
        sx[tid] = (node < N_NODES) ? x[(size_t)node * IN_DIM + k] : 0.f;
    }
    __syncthreads();
    float bc = bin[tid];
    for (int n = 0; n < 8; n++) {
        int node = base + n;
        if (node >= N_NODES) break;
        float sum = bc;
#pragma unroll
        for (int k = 0; k < IN_DIM; k++) sum += sx[n * IN_DIM + k] * sW[k * HID + tid];
        g_h[(size_t)node * HID + tid] = sum;
    }
}

// ---------------- propagate (MLP=4 gather) ----------------
__global__ void k_gather() {
    int warp = threadIdx.x >> 5, lane = threadIdx.x & 31;
    int d = blockIdx.x * 8 + warp;
    if (d >= N_NODES) return;
    int start = g_off[d], end = g_off[d + 1];
    float dd = g_dis[d];
    const float4* hv = (const float4*)g_h;
    float4 acc = hv[(size_t)d * 32 + lane];
    acc.x *= dd; acc.y *= dd; acc.z *= dd; acc.w *= dd;
    for (int j = start; j < end; j += 32) {
        int2 ew = make_int2(0, 0);
        if (j + lane < end) ew = g_csr[j + lane];
        int cnt = min(32, end - j);
        int t = 0;
        for (; t + 4 <= cnt; t += 4) {
            int s0 = __shfl_sync(0xffffffffu, ew.x, t);
            int s1 = __shfl_sync(0xffffffffu, ew.x, t + 1);
            int s2 = __shfl_sync(0xffffffffu, ew.x, t + 2);
            int s3 = __shfl_sync(0xffffffffu, ew.x, t + 3);
            float w0 = __int_as_float(__shfl_sync(0xffffffffu, ew.y, t));
            float w1 = __int_as_float(__shfl_sync(0xffffffffu, ew.y, t + 1));
            float w2 = __int_as_float(__shfl_sync(0xffffffffu, ew.y, t + 2));
            float w3 = __int_as_float(__shfl_sync(0xffffffffu, ew.y, t + 3));
            float4 v0 = hv[(size_t)s0 * 32 + lane];
            float4 v1 = hv[(size_t)s1 * 32 + lane];
            float4 v2 = hv[(size_t)s2 * 32 + lane];
            float4 v3 = hv[(size_t)s3 * 32 + lane];
            acc.x += w0 * v0.x; acc.y += w0 * v0.y; acc.z += w0 * v0.z; acc.w += w0 * v0.w;
            acc.x += w1 * v1.x; acc.y += w1 * v1.y; acc.z += w1 * v1.z; acc.w += w1 * v1.w;
            acc.x += w2 * v2.x; acc.y += w2 * v2.y; acc.z += w2 * v2.z; acc.w += w2 * v2.w;
            acc.x += w3 * v3.x; acc.y += w3 * v3.y; acc.z += w3 * v3.z; acc.w += w3 * v3.w;
        }
        for (; t < cnt; t++) {
            int   s = __shfl_sync(0xffffffffu, ew.x, t);
            float w = __int_as_float(__shfl_sync(0xffffffffu, ew.y, t));
            float4 v = hv[(size_t)s * 32 + lane];
            acc.x += w * v.x; acc.y += w * v.y; acc.z += w * v.z; acc.w += w * v.w;
        }
    }
    acc.x *= dd; acc.y *= dd; acc.z *= dd; acc.w *= dd;
    ((float4*)g_p)[(size_t)d * 32 + lane] = acc;
}

// ---------------- transform via mma.sync bf16 m16n8k16, dual hi/lo split ----------------
// Block: 128-row tile, 256 threads = 8 warps (4 row-groups x 2 col-groups).
// Warp (wr, wc): rows [32wr, 32wr+32) x cols [64wc, 64wc+64).
// smem (u32 units):
//   sAh [128][68]  u32 = bf16x2 hi-pairs of p (k-pairs 0..63)
//   sAl [128][68]  u32 = bf16x2 lo-pairs
//   sB  [64][136]  u64 = (hi-pair | lo-pair<<32) of W, [k-pair][n]
#define ASTR 68
#define BSTR 136
#define SM_AH 0
#define SM_AL (128 * ASTR)
#define SM_B_U32 (256 * ASTR)
#define SM_U32_TOTAL (256 * ASTR + 64 * BSTR * 2)

__global__ void __launch_bounds__(256) k_transform_bf(
        const float* __restrict__ W, const float* __restrict__ bias,
        const float* __restrict__ gamma, const float* __restrict__ beta,
        float* __restrict__ out, int add_res) {
    extern __shared__ uint32_t smem[];
    __shared__ float sBias[HID], sG[HID], sBe[HID];
    __shared__ float psum[2][128], psq[2][128];
    int tid = threadIdx.x;
    int rbase = blockIdx.x * 128;

    for (int i = tid; i < HID; i += 256) {
        sBias[i] = bias[i];
        sG[i] = gamma[i];
        sBe[i] = beta[i];
    }
    // stage W: sB[kp][n] = (hi(W[2kp][n]),hi(W[2kp+1][n])) | (lo...)<<32
    {
        ull* sB = (ull*)(smem + SM_B_U32);
        for (int i = tid; i < 64 * HID; i += 256) {
            int kp = i >> 7, n = i & 127;
            uint16_t h0, l0, h1, l1;
            split_bf16(W[(2 * kp) * HID + n], h0, l0);
            split_bf16(W[(2 * kp + 1) * HID + n], h1, l1);
            uint32_t hp = (uint32_t)h0 | ((uint32_t)h1 << 16);
            uint32_t lp = (uint32_t)l0 | ((uint32_t)l1 << 16);
            sB[kp * BSTR + n] = (ull)hp | ((ull)lp << 32);
        }
    }
    // stage A hi/lo pairs from g_p
    {
        const float2* p2 = (const float2*)g_p;
        for (int i = tid; i < 128 * 64; i += 256) {
            int r = i >> 6, kp = i & 63;
            float2 v = p2[(size_t)(rbase + r) * 64 + kp];
            uint16_t h0, l0, h1, l1;
            split_bf16(v.x, h0, l0);
            split_bf16(v.y, h1, l1);
            smem[SM_AH + r * ASTR + kp] = (uint32_t)h0 | ((uint32_t)h1 << 16);
            smem[SM_AL + r * ASTR + kp] = (uint32_t)l0 | ((uint32_t)l1 << 16);
        }
    }
    __syncthreads();

    int warp = tid >> 5, lane = tid & 31;
    int grp = lane >> 2, qid = lane & 3;
    int wr = warp >> 1, wc = warp & 1;
    int row0 = wr * 32;
    int col0 = wc * 64;

    float acc[2][8][4];
#pragma unroll
    for (int m = 0; m < 2; m++)
#pragma unroll
        for (int n = 0; n < 8; n++)
#pragma unroll
            for (int c = 0; c < 4; c++) acc[m][n][c] = 0.f;

    const uint32_t* sAh = smem + SM_AH;
    const uint32_t* sAl = smem + SM_AL;
    const ull* sB = (const ull*)(smem + SM_B_U32);

#pragma unroll 2
    for (int ks = 0; ks < 8; ks++) {
        int kb = 8 * ks;   // k-pair base for this k16 step
        uint32_t ah[2][4], al[2][4];
#pragma unroll
        for (int m = 0; m < 2; m++) {
            int raA = (row0 + m * 16 + grp) * ASTR + kb;
            int raB = raA + 8 * ASTR;
            ah[m][0] = sAh[raA + qid];
            ah[m][1] = sAh[raB + qid];
            ah[m][2] = sAh[raA + qid + 4];
            ah[m][3] = sAh[raB + qid + 4];
            al[m][0] = sAl[raA + qid];
            al[m][1] = sAl[raB + qid];
            al[m][2] = sAl[raA + qid + 4];
            al[m][3] = sAl[raB + qid + 4];
        }
#pragma unroll
        for (int n = 0; n < 8; n++) {
            ull bv0 = sB[(kb + qid) * BSTR + col0 + n * 8 + grp];
            ull bv1 = sB[(kb + qid + 4) * BSTR + col0 + n * 8 + grp];
            uint32_t b0h = (uint32_t)bv0, b0l = (uint32_t)(bv0 >> 32);
            uint32_t b1h = (uint32_t)bv1, b1l = (uint32_t)(bv1 >> 32);
            mma_bf16(acc[0][n], ah[0], b0h, b1h);
            mma_bf16(acc[0][n], ah[0], b0l, b1l);
            mma_bf16(acc[0][n], al[0], b0h, b1h);
            mma_bf16(acc[1][n], ah[1], b0h, b1h);
            mma_bf16(acc[1][n], ah[1], b0l, b1l);
            mma_bf16(acc[1][n], al[1], b0h, b1h);
        }
    }

    // bias add + per-row partial sums over this warp's 64 cols
    float s[4] = {0.f, 0.f, 0.f, 0.f}, q[4] = {0.f, 0.f, 0.f, 0.f};
#pragma unroll
    for (int m = 0; m < 2; m++)
#pragma unroll
        for (int n = 0; n < 8; n++) {
            int c0 = col0 + n * 8 + 2 * qid;
            float b0 = sBias[c0], b1 = sBias[c0 + 1];
            acc[m][n][0] += b0; acc[m][n][1] += b1;
            acc[m][n][2] += b0; acc[m][n][3] += b1;
            s[m * 2]     += acc[m][n][0] + acc[m][n][1];
            q[m * 2]     += acc[m][n][0] * acc[m][n][0] + acc[m][n][1] * acc[m][n][1];
            s[m * 2 + 1] += acc[m][n][2] + acc[m][n][3];
            q[m * 2 + 1] += acc[m][n][2] * acc[m][n][2] + acc[m][n][3] * acc[m][n][3];
        }
#pragma unroll
    for (int o = 1; o <= 2; o <<= 1)
#pragma unroll
        for (int i = 0; i < 4; i++) {
            s[i] += __shfl_xor_sync(0xffffffffu, s[i], o);
            q[i] += __shfl_xor_sync(0xffffffffu, q[i], o);
        }
    if (qid == 0) {
#pragma unroll
        for (int i = 0; i < 4; i++) {
            int r = row0 + (i >> 1) * 16 + grp + (i & 1) * 8;
            psum[wc][r] = s[i];
            psq[wc][r] = q[i];
        }
    }
    __syncthreads();

    float mu[4], rstd[4];
#pragma unroll
    for (int i = 0; i < 4; i++) {
        int r = row0 + (i >> 1) * 16 + grp + (i & 1) * 8;
        float tot = psum[0][r] + psum[1][r];
        float tq  = psq[0][r] + psq[1][r];
        mu[i] = tot * (1.f / 128.f);
        rstd[i] = rsqrtf(fmaxf(tq * (1.f / 128.f) - mu[i] * mu[i], 0.f) + LN_EPS);
    }

    // LN + ReLU + residual + store (float2 per quad)
#pragma unroll
    for (int m = 0; m < 2; m++) {
        int ra = row0 + m * 16 + grp;
        int rb = ra + 8;
        int na = rbase + ra, nb2 = rbase + rb;
#pragma unroll
        for (int n = 0; n < 8; n++) {
            int c0 = col0 + n * 8 + 2 * qid;
            float g0 = sG[c0], g1 = sG[c0 + 1], e0 = sBe[c0], e1 = sBe[c0 + 1];
            if (na < N_NODES) {
                float2 o;
                o.x = fmaxf((acc[m][n][0] - mu[m * 2]) * rstd[m * 2] * g0 + e0, 0.f);
                o.y = fmaxf((acc[m][n][1] - mu[m * 2]) * rstd[m * 2] * g1 + e1, 0.f);
                if (add_res) {
                    float2 hp = *(const float2*)(g_h + (size_t)na * HID + c0);
                    o.x += hp.x; o.y += hp.y;
                }
                *(float2*)(out + (size_t)na * HID + c0) = o;
            }
            if (nb2 < N_NODES) {
                float2 o;
                o.x = fmaxf((acc[m][n][2] - mu[m * 2 + 1]) * rstd[m * 2 + 1] * g0 + e0, 0.f);
                o.y = fmaxf((acc[m][n][3] - mu[m * 2 + 1]) * rstd[m * 2 + 1] * g1 + e1, 0.f);
                if (add_res) {
                    float2 hp = *(const float2*)(g_h + (size_t)nb2 * HID + c0);
                    o.x += hp.x; o.y += hp.y;
                }
                *(float2*)(out + (size_t)nb2 * HID + c0) = o;
            }
        }
    }
}

// ---------------- launch ----------------
extern "C" void kernel_launch(void* const* d_in, const int* in_sizes, int n_in,
                              void* d_out, int out_size) {
    const float* x   = (const float*)d_in[0];
    const void*  eix = d_in[1];
    const float* Win = (const float*)d_in[2];
    const float* bin = (const float*)d_in[3];
    const float* Wc  = (const float*)d_in[4];
    const float* bc  = (const float*)d_in[5];
    const float* lg  = (const float*)d_in[6];
    const float* lb  = (const float*)d_in[7];
    int E = in_sizes[1] / 2;

    static bool attr_set = false;  // idempotent attribute set
    if (!attr_set) {
        cudaFuncSetAttribute(k_transform_bf, cudaFuncAttributeMaxDynamicSharedMemorySize,
                             SM_U32_TOTAL * (int)sizeof(uint32_t));
        attr_set = true;
    }

    void* h_addr = nullptr;
    cudaGetSymbolAddress(&h_addr, g_h);

    k_zero_detect<<<(N_NODES + 255) / 256, 256>>>((const unsigned int*)eix, 4096);
    k_hist<<<(E + 255) / 256, 256>>>(eix, E);
    int nb = (N_NODES + SCAN_B - 1) / SCAN_B;
    k_scan1<<<nb, SCAN_B>>>();
    k_scan2<<<1, 256>>>(nb);
    k_scan3<<<nb, SCAN_B>>>();
    k_fill<<<(E + 255) / 256, 256>>>(eix, E);

    k_proj<<<(N_NODES + 7) / 8, 128>>>(x, Win, bin);

    int tiles = N_ROWS_PAD / 128;  // 782
    size_t tsmem = SM_U32_TOTAL * sizeof(uint32_t);  // ~136KB
    for (int l = 0; l < 3; l++) {
        k_gather<<<(N_NODES + 7) / 8, 256>>>();
        float* out = (l == 2) ? (float*)d_out : (float*)h_addr;
        k_transform_bf<<<tiles, 256, tsmem>>>(
            Wc + (size_t)l * HID * HID, bc + l * HID, lg + l * HID, lb + l * HID,
            out, (l > 0) ? 1 : 0);
    }
}

// round 10
// speedup vs baseline: 1.3972x; 1.0226x over previous
#include <cuda_runtime.h>
#include <cuda_bf16.h>
#include <cstdint>

#define N_NODES 100000
#define N_ROWS_PAD 100096              // 1564 * 64
#define N_EDGES 1600000
#define HID     128
#define IN_DIM  16
#define LN_EPS  1e-5f
#define SCAN_B  512

typedef unsigned long long ull;

// ---------------- device scratch ----------------
__device__ int   g_deg[N_NODES];
__device__ float g_dis[N_NODES];
__device__ int   g_off[N_NODES + 1];
__device__ int2  g_csr[N_EDGES];
__device__ float g_h[(size_t)N_NODES * HID];
__device__ float g_p[(size_t)N_ROWS_PAD * HID];   // padded, .bss zeros
__device__ int   g_bsum[256];
__device__ int   g_wide;

// ---------------- bf16 split helpers ----------------
__device__ __forceinline__ void split_bf16(float x, uint16_t& hi, uint16_t& lo) {
    __nv_bfloat16 h = __float2bfloat16(x);
    float r = x - __bfloat162float(h);
    __nv_bfloat16 l = __float2bfloat16(r);
    hi = __bfloat16_as_ushort(h);
    lo = __bfloat16_as_ushort(l);
}
__device__ __forceinline__ void mma_bf16(float c[4], const uint32_t a[4],
                                         uint32_t b0, uint32_t b1) {
    asm("mma.sync.aligned.m16n8k16.row.col.f32.bf16.bf16.f32 "
        "{%0,%1,%2,%3}, {%4,%5,%6,%7}, {%8,%9}, {%0,%1,%2,%3};"
        : "+f"(c[0]), "+f"(c[1]), "+f"(c[2]), "+f"(c[3])
        : "r"(a[0]), "r"(a[1]), "r"(a[2]), "r"(a[3]), "r"(b0), "r"(b1));
}

// ---------------- zero + edge dtype detection (merged) ----------------
__global__ void k_zero_detect(const unsigned int* __restrict__ e32, int nwords) {
    int i = blockIdx.x * blockDim.x + threadIdx.x;
    if (i < N_NODES) g_deg[i] = 0;
    if (blockIdx.x == 0) {
        __shared__ unsigned int s_or;
        if (threadIdx.x == 0) s_or = 0u;
        __syncthreads();
        unsigned int v = 0u;
        for (int j = threadIdx.x * 2 + 1; j < nwords; j += blockDim.x * 2) v |= e32[j];
        atomicOr(&s_or, v);
        __syncthreads();
        if (threadIdx.x == 0) g_wide = (s_or == 0u) ? 1 : 0;
    }
}

__device__ __forceinline__ int load_edge(const void* eidx, long idx, int wide) {
    if (wide) return (int)((const long long*)eidx)[idx];
    return ((const int*)eidx)[idx];
}

// ---------------- CSR build ----------------
__global__ void k_hist(const void* __restrict__ eidx, int E) {
    int i = blockIdx.x * blockDim.x + threadIdx.x;
    if (i >= E) return;
    atomicAdd(&g_deg[load_edge(eidx, (long)E + i, g_wide)], 1);
}
__global__ void k_scan1() {
    __shared__ int s[SCAN_B];
    int tid = threadIdx.x;
    int i = blockIdx.x * SCAN_B + tid;
    s[tid] = (i < N_NODES) ? g_deg[i] : 0;
    __syncthreads();
    for (int o = SCAN_B / 2; o > 0; o >>= 1) {
        if (tid < o) s[tid] += s[tid + o];
        __syncthreads();
    }
    if (tid == 0) g_bsum[blockIdx.x] = s[0];
}
__global__ void k_scan2(int nb) {
    __shared__ int s[256];
    int tid = threadIdx.x;
    int v = (tid < nb) ? g_bsum[tid] : 0;
    s[tid] = v;
    __syncthreads();
    for (int o = 1; o < 256; o <<= 1) {
        int t = (tid >= o) ? s[tid - o] : 0;
        __syncthreads();
        s[tid] += t;
        __syncthreads();
    }
    if (tid < nb) g_bsum[tid] = s[tid] - v;
}
__global__ void k_scan3() {
    __shared__ int s[SCAN_B];
    int tid = threadIdx.x;
    int i = blockIdx.x * SCAN_B + tid;
    int v = (i < N_NODES) ? g_deg[i] : 0;
    s[tid] = v;
    __syncthreads();
    for (int o = 1; o < SCAN_B; o <<= 1) {
        int t = (tid >= o) ? s[tid - o] : 0;
        __syncthreads();
        s[tid] += t;
        __syncthreads();
    }
    int off = g_bsum[blockIdx.x] + s[tid] - v;
    if (i < N_NODES) {
        g_off[i] = off;
        g_dis[i] = rsqrtf((float)(v + 1));
        if (i == N_NODES - 1) g_off[N_NODES] = off + v;
        g_deg[i] = off;
    }
}
__global__ void k_fill(const void* __restrict__ eidx, int E) {
    int i = blockIdx.x * blockDim.x + threadIdx.x;
    if (i >= E) return;
    int wide = g_wide;
    int sidx = load_edge(eidx, i, wide);
    int didx = load_edge(eidx, (long)E + i, wide);
    int pos = atomicAdd(&g_deg[didx], 1);
    g_csr[pos] = make_int2(sidx, __float_as_int(g_dis[sidx]));
}

// ---------------- input projection ----------------
__global__ void k_proj(const float* __restrict__ x, const float* __restrict__ Win,
                       const float* __restrict__ bin) {
    __shared__ float sW[IN_DIM * HID];
    __shared__ float sx[8 * IN_DIM];
    int tid = threadIdx.x;
    for (int i = tid; i < IN_DIM * HID; i += 128) sW[i] = Win[i];
    int base = blockIdx.x * 8;
    {
        int n = tid / IN_DIM, k = tid % IN_DIM;
        int node = base + n;
        sx[tid] = (node < N_NODES) ? x[(size_t)node * IN_DIM + k] : 0.f;
    }
    __syncthreads();
    float bc = bin[tid];
    for (int n = 0; n < 8; n++) {
        int node = base + n;
        if (node >= N_NODES) break;
        float sum = bc;
#pragma unroll
        for (int k = 0; k < IN_DIM; k++) sum += sx[n * IN_DIM + k] * sW[k * HID + tid];
        g_h[(size_t)node * HID + tid] = sum;
    }
}

// ---------------- propagate (MLP=4 gather) ----------------
__global__ void k_gather() {
    int warp = threadIdx.x >> 5, lane = threadIdx.x & 31;
    int d = blockIdx.x * 8 + warp;
    if (d >= N_NODES) return;
    int start = g_off[d], end = g_off[d + 1];
    float dd = g_dis[d];
    const float4* hv = (const float4*)g_h;
    float4 acc = hv[(size_t)d * 32 + lane];
    acc.x *= dd; acc.y *= dd; acc.z *= dd; acc.w *= dd;
    for (int j = start; j < end; j += 32) {
        int2 ew = make_int2(0, 0);
        if (j + lane < end) ew = g_csr[j + lane];
        int cnt = min(32, end - j);
        int t = 0;
        for (; t + 4 <= cnt; t += 4) {
            int s0 = __shfl_sync(0xffffffffu, ew.x, t);
            int s1 = __shfl_sync(0xffffffffu, ew.x, t + 1);
            int s2 = __shfl_sync(0xffffffffu, ew.x, t + 2);
            int s3 = __shfl_sync(0xffffffffu, ew.x, t + 3);
            float w0 = __int_as_float(__shfl_sync(0xffffffffu, ew.y, t));
            float w1 = __int_as_float(__shfl_sync(0xffffffffu, ew.y, t + 1));
            float w2 = __int_as_float(__shfl_sync(0xffffffffu, ew.y, t + 2));
            float w3 = __int_as_float(__shfl_sync(0xffffffffu, ew.y, t + 3));
            float4 v0 = hv[(size_t)s0 * 32 + lane];
            float4 v1 = hv[(size_t)s1 * 32 + lane];
            float4 v2 = hv[(size_t)s2 * 32 + lane];
            float4 v3 = hv[(size_t)s3 * 32 + lane];
            acc.x += w0 * v0.x; acc.y += w0 * v0.y; acc.z += w0 * v0.z; acc.w += w0 * v0.w;
            acc.x += w1 * v1.x; acc.y += w1 * v1.y; acc.z += w1 * v1.z; acc.w += w1 * v1.w;
            acc.x += w2 * v2.x; acc.y += w2 * v2.y; acc.z += w2 * v2.z; acc.w += w2 * v2.w;
            acc.x += w3 * v3.x; acc.y += w3 * v3.y; acc.z += w3 * v3.z; acc.w += w3 * v3.w;
        }
        for (; t < cnt; t++) {
            int   s = __shfl_sync(0xffffffffu, ew.x, t);
            float w = __int_as_float(__shfl_sync(0xffffffffu, ew.y, t));
            float4 v = hv[(size_t)s * 32 + lane];
            acc.x += w * v.x; acc.y += w * v.y; acc.z += w * v.z; acc.w += w * v.w;
        }
    }
    acc.x *= dd; acc.y *= dd; acc.z *= dd; acc.w *= dd;
    ((float4*)g_p)[(size_t)d * 32 + lane] = acc;
}

// ---------------- transform via mma.sync bf16 m16n8k16, dual hi/lo split ----------------
// Block: 64-row tile, 256 threads = 8 warps (4 row-groups x 2 col-groups).
// Warp (wr, wc): rows [16wr, 16wr+16) x cols [64wc, 64wc+64).
// smem (u32 units):
//   sAh [64][68]  u32 = bf16x2 hi-pairs of p (k-pairs 0..63)
//   sAl [64][68]  u32 = bf16x2 lo-pairs
//   sB  [64][136] u64 = (hi-pair | lo-pair<<32) of W, [k-pair][n]
// Total dynamic: 64*68*4*2 + 64*136*8 = 34.8KB + 69.6KB = 104.4KB -> 2 blocks/SM.
#define ASTR 68
#define BSTR 136
#define SM_AH 0
#define SM_AL (64 * ASTR)
#define SM_B_U32 (128 * ASTR)
#define SM_U32_TOTAL (128 * ASTR + 64 * BSTR * 2)

__global__ void __launch_bounds__(256, 2) k_transform_bf(
        const float* __restrict__ W, const float* __restrict__ bias,
        const float* __restrict__ gamma, const float* __restrict__ beta,
        float* __restrict__ out, int add_res) {
    extern __shared__ uint32_t smem[];
    __shared__ float sBias[HID], sG[HID], sBe[HID];
    __shared__ float psum[2][64], psq[2][64];
    int tid = threadIdx.x;
    int rbase = blockIdx.x * 64;

    for (int i = tid; i < HID; i += 256) {
        sBias[i] = bias[i];
        sG[i] = gamma[i];
        sBe[i] = beta[i];
    }
    // stage W: sB[kp][n] = (hi(W[2kp][n]),hi(W[2kp+1][n])) | (lo...)<<32
    {
        ull* sB = (ull*)(smem + SM_B_U32);
        for (int i = tid; i < 64 * HID; i += 256) {
            int kp = i >> 7, n = i & 127;
            uint16_t h0, l0, h1, l1;
            split_bf16(W[(2 * kp) * HID + n], h0, l0);
            split_bf16(W[(2 * kp + 1) * HID + n], h1, l1);
            uint32_t hp = (uint32_t)h0 | ((uint32_t)h1 << 16);
            uint32_t lp = (uint32_t)l0 | ((uint32_t)l1 << 16);
            sB[kp * BSTR + n] = (ull)hp | ((ull)lp << 32);
        }
    }
    // stage A hi/lo pairs from g_p
    {
        const float2* p2 = (const float2*)g_p;
        for (int i = tid; i < 64 * 64; i += 256) {
            int r = i >> 6, kp = i & 63;
            float2 v = p2[(size_t)(rbase + r) * 64 + kp];
            uint16_t h0, l0, h1, l1;
            split_bf16(v.x, h0, l0);
            split_bf16(v.y, h1, l1);
            smem[SM_AH + r * ASTR + kp] = (uint32_t)h0 | ((uint32_t)h1 << 16);
            smem[SM_AL + r * ASTR + kp] = (uint32_t)l0 | ((uint32_t)l1 << 16);
        }
    }
    __syncthreads();

    int warp = tid >> 5, lane = tid & 31;
    int grp = lane >> 2, qid = lane & 3;
    int wr = warp >> 1, wc = warp & 1;
    int row0 = wr * 16;
    int col0 = wc * 64;

    float acc[8][4];
#pragma unroll
    for (int n = 0; n < 8; n++)
#pragma unroll
        for (int c = 0; c < 4; c++) acc[n][c] = 0.f;

    const uint32_t* sAh = smem + SM_AH;
    const uint32_t* sAl = smem + SM_AL;
    const ull* sB = (const ull*)(smem + SM_B_U32);

#pragma unroll 2
    for (int ks = 0; ks < 8; ks++) {
        int kb = 8 * ks;   // k-pair base for this k16 step
        int raA = (row0 + grp) * ASTR + kb;
        int raB = raA + 8 * ASTR;
        uint32_t ah[4], al[4];
        ah[0] = sAh[raA + qid];
        ah[1] = sAh[raB + qid];
        ah[2] = sAh[raA + qid + 4];
        ah[3] = sAh[raB + qid + 4];
        al[0] = sAl[raA + qid];
        al[1] = sAl[raB + qid];
        al[2] = sAl[raA + qid + 4];
        al[3] = sAl[raB + qid + 4];

        uint32_t bh0[8], bh1[8], bl0[8], bl1[8];
#pragma unroll
        for (int n = 0; n < 8; n++) {
            ull bv0 = sB[(kb + qid) * BSTR + col0 + n * 8 + grp];
            ull bv1 = sB[(kb + qid + 4) * BSTR + col0 + n * 8 + grp];
            bh0[n] = (uint32_t)bv0; bl0[n] = (uint32_t)(bv0 >> 32);
            bh1[n] = (uint32_t)bv1; bl1[n] = (uint32_t)(bv1 >> 32);
        }
        // pass-separated: each acc's dependent mmas are 8 issues apart
#pragma unroll
        for (int n = 0; n < 8; n++) mma_bf16(acc[n], ah, bh0[n], bh1[n]);
#pragma unroll
        for (int n = 0; n < 8; n++) mma_bf16(acc[n], ah, bl0[n], bl1[n]);
#pragma unroll
        for (int n = 0; n < 8; n++) mma_bf16(acc[n], al, bh0[n], bh1[n]);
    }

    // bias add + per-row partial sums over this warp's 64 cols
    float s[2] = {0.f, 0.f}, q[2] = {0.f, 0.f};
#pragma unroll
    for (int n = 0; n < 8; n++) {
        int c0 = col0 + n * 8 + 2 * qid;
        float b0 = sBias[c0], b1 = sBias[c0 + 1];
        acc[n][0] += b0; acc[n][1] += b1;
        acc[n][2] += b0; acc[n][3] += b1;
        s[0] += acc[n][0] + acc[n][1];
        q[0] += acc[n][0] * acc[n][0] + acc[n][1] * acc[n][1];
        s[1] += acc[n][2] + acc[n][3];
        q[1] += acc[n][2] * acc[n][2] + acc[n][3] * acc[n][3];
    }
#pragma unroll
    for (int o = 1; o <= 2; o <<= 1)
#pragma unroll
        for (int i = 0; i < 2; i++) {
            s[i] += __shfl_xor_sync(0xffffffffu, s[i], o);
            q[i] += __shfl_xor_sync(0xffffffffu, q[i], o);
        }
    if (qid == 0) {
#pragma unroll
        for (int i = 0; i < 2; i++) {
            int r = row0 + grp + i * 8;
            psum[wc][r] = s[i];
            psq[wc][r] = q[i];
        }
    }
    __syncthreads();

    float mu[2], rstd[2];
#pragma unroll
    for (int i = 0; i < 2; i++) {
        int r = row0 + grp + i * 8;
        float tot = psum[0][r] + psum[1][r];
        float tq  = psq[0][r] + psq[1][r];
        mu[i] = tot * (1.f / 128.f);
        rstd[i] = rsqrtf(fmaxf(tq * (1.f / 128.f) - mu[i] * mu[i], 0.f) + LN_EPS);
    }

    // LN + ReLU + residual + store (float2 per quad)
    int ra = row0 + grp;
    int rb = ra + 8;
    int na = rbase + ra, nb2 = rbase + rb;
#pragma unroll
    for (int n = 0; n < 8; n++) {
        int c0 = col0 + n * 8 + 2 * qid;
        float g0 = sG[c0], g1 = sG[c0 + 1], e0 = sBe[c0], e1 = sBe[c0 + 1];
        if (na < N_NODES) {
            float2 o;
            o.x = fmaxf((acc[n][0] - mu[0]) * rstd[0] * g0 + e0, 0.f);
            o.y = fmaxf((acc[n][1] - mu[0]) * rstd[0] * g1 + e1, 0.f);
            if (add_res) {
                float2 hp = *(const float2*)(g_h + (size_t)na * HID + c0);
                o.x += hp.x; o.y += hp.y;
            }
            *(float2*)(out + (size_t)na * HID + c0) = o;
        }
        if (nb2 < N_NODES) {
            float2 o;
            o.x = fmaxf((acc[n][2] - mu[1]) * rstd[1] * g0 + e0, 0.f);
            o.y = fmaxf((acc[n][3] - mu[1]) * rstd[1] * g1 + e1, 0.f);
            if (add_res) {
                float2 hp = *(const float2*)(g_h + (size_t)nb2 * HID + c0);
                o.x += hp.x; o.y += hp.y;
            }
            *(float2*)(out + (size_t)nb2 * HID + c0) = o;
        }
    }
}

// ---------------- launch ----------------
extern "C" void kernel_launch(void* const* d_in, const int* in_sizes, int n_in,
                              void* d_out, int out_size) {
    const float* x   = (const float*)d_in[0];
    const void*  eix = d_in[1];
    const float* Win = (const float*)d_in[2];
    const float* bin = (const float*)d_in[3];
    const float* Wc  = (const float*)d_in[4];
    const float* bc  = (const float*)d_in[5];
    const float* lg  = (const float*)d_in[6];
    const float* lb  = (const float*)d_in[7];
    int E = in_sizes[1] / 2;

    static bool attr_set = false;  // idempotent attribute set
    if (!attr_set) {
        cudaFuncSetAttribute(k_transform_bf, cudaFuncAttributeMaxDynamicSharedMemorySize,
                             SM_U32_TOTAL * (int)sizeof(uint32_t));
        attr_set = true;
    }

    void* h_addr = nullptr;
    cudaGetSymbolAddress(&h_addr, g_h);

    k_zero_detect<<<(N_NODES + 255) / 256, 256>>>((const unsigned int*)eix, 4096);
    k_hist<<<(E + 255) / 256, 256>>>(eix, E);
    int nb = (N_NODES + SCAN_B - 1) / SCAN_B;
    k_scan1<<<nb, SCAN_B>>>();
    k_scan2<<<1, 256>>>(nb);
    k_scan3<<<nb, SCAN_B>>>();
    k_fill<<<(E + 255) / 256, 256>>>(eix, E);

    k_proj<<<(N_NODES + 7) / 8, 128>>>(x, Win, bin);

    int tiles = N_ROWS_PAD / 64;  // 1564
    size_t tsmem = SM_U32_TOTAL * sizeof(uint32_t);  // ~104.4KB
    for (int l = 0; l < 3; l++) {
        k_gather<<<(N_NODES + 7) / 8, 256>>>();
        float* out = (l == 2) ? (float*)d_out : (float*)h_addr;
        k_transform_bf<<<tiles, 256, tsmem>>>(
            Wc + (size_t)l * HID * HID, bc + l * HID, lg + l * HID, lb + l * HID,
            out, (l > 0) ? 1 : 0);
    }
}

// round 11
// speedup vs baseline: 1.4530x; 1.0400x over previous
#include <cuda_runtime.h>
#include <cuda_bf16.h>
#include <cuda_fp16.h>
#include <cstdint>

#define N_NODES 100000
#define N_ROWS_PAD 100096              // 1564 * 64
#define N_EDGES 1600000
#define HID     128
#define IN_DIM  16
#define LN_EPS  1e-5f
#define SCAN_B  512

typedef unsigned long long ull;

// ---------------- device scratch ----------------
__device__ int    g_deg[N_NODES];
__device__ float  g_dis[N_NODES];
__device__ int    g_off[N_NODES];
__device__ int    g_end[N_NODES];
__device__ int2   g_csr[N_EDGES];
__device__ float  g_h[(size_t)N_NODES * HID];     // f32 features (residual source)
__device__ __half g_hh[(size_t)N_NODES * HID];    // fp16 copy (gather operand)
__device__ float  g_p[(size_t)N_ROWS_PAD * HID];  // padded, .bss zeros
__device__ int    g_total;
__device__ int    g_wide;

// ---------------- bf16 split helpers ----------------
__device__ __forceinline__ void split_bf16(float x, uint16_t& hi, uint16_t& lo) {
    __nv_bfloat16 h = __float2bfloat16(x);
    float r = x - __bfloat162float(h);
    __nv_bfloat16 l = __float2bfloat16(r);
    hi = __bfloat16_as_ushort(h);
    lo = __bfloat16_as_ushort(l);
}
__device__ __forceinline__ void mma_bf16(float c[4], const uint32_t a[4],
                                         uint32_t b0, uint32_t b1) {
    asm("mma.sync.aligned.m16n8k16.row.col.f32.bf16.bf16.f32 "
        "{%0,%1,%2,%3}, {%4,%5,%6,%7}, {%8,%9}, {%0,%1,%2,%3};"
        : "+f"(c[0]), "+f"(c[1]), "+f"(c[2]), "+f"(c[3])
        : "r"(a[0]), "r"(a[1]), "r"(a[2]), "r"(a[3]), "r"(b0), "r"(b1));
}

// ---------------- zero + edge dtype detection (merged) ----------------
__global__ void k_zero_detect(const unsigned int* __restrict__ e32, int nwords) {
    int i = blockIdx.x * blockDim.x + threadIdx.x;
    if (i < N_NODES) g_deg[i] = 0;
    if (i == 0) g_total = 0;
    if (blockIdx.x == 0) {
        __shared__ unsigned int s_or;
        if (threadIdx.x == 0) s_or = 0u;
        __syncthreads();
        unsigned int v = 0u;
        for (int j = threadIdx.x * 2 + 1; j < nwords; j += blockDim.x * 2) v |= e32[j];
        atomicOr(&s_or, v);
        __syncthreads();
        if (threadIdx.x == 0) g_wide = (s_or == 0u) ? 1 : 0;
    }
}

__device__ __forceinline__ int load_edge(const void* eidx, long idx, int wide) {
    if (wide) return (int)((const long long*)eidx)[idx];
    return ((const int*)eidx)[idx];
}

// ---------------- CSR build ----------------
__global__ void k_hist(const void* __restrict__ eidx, int E) {
    int i = blockIdx.x * blockDim.x + threadIdx.x;
    if (i >= E) return;
    atomicAdd(&g_deg[load_edge(eidx, (long)E + i, g_wide)], 1);
}

// block scan + one global atomic per block -> disjoint (unordered) CSR ranges
__global__ void k_alloc() {
    __shared__ int s[SCAN_B];
    __shared__ int sbase;
    int tid = threadIdx.x;
    int i = blockIdx.x * SCAN_B + tid;
    int v = (i < N_NODES) ? g_deg[i] : 0;
    s[tid] = v;
    __syncthreads();
    for (int o = 1; o < SCAN_B; o <<= 1) {
        int t = (tid >= o) ? s[tid - o] : 0;
        __syncthreads();
        s[tid] += t;
        __syncthreads();
    }
    if (tid == SCAN_B - 1) sbase = atomicAdd(&g_total, s[SCAN_B - 1]);
    __syncthreads();
    int off = sbase + s[tid] - v;  // exclusive within block + block base
    if (i < N_NODES) {
        g_off[i] = off;
        g_end[i] = off + v;
        g_dis[i] = rsqrtf((float)(v + 1));
        g_deg[i] = off;  // fill cursor
    }
}

__global__ void k_fill(const void* __restrict__ eidx, int E) {
    int i = blockIdx.x * blockDim.x + threadIdx.x;
    if (i >= E) return;
    int wide = g_wide;
    int sidx = load_edge(eidx, i, wide);
    int didx = load_edge(eidx, (long)E + i, wide);
    int pos = atomicAdd(&g_deg[didx], 1);
    g_csr[pos] = make_int2(sidx, __float_as_int(g_dis[sidx]));
}

// ---------------- input projection (writes f32 + fp16 copies) ----------------
__global__ void k_proj(const float* __restrict__ x, const float* __restrict__ Win,
                       const float* __restrict__ bin) {
    __shared__ float sW[IN_DIM * HID];
    __shared__ float sx[8 * IN_DIM];
    int tid = threadIdx.x;
    for (int i = tid; i < IN_DIM * HID; i += 128) sW[i] = Win[i];
    int base = blockIdx.x * 8;
    {
        int n = tid / IN_DIM, k = tid % IN_DIM;
        int node = base + n;
        sx[tid] = (node < N_NODES) ? x[(size_t)node * IN_DIM + k] : 0.f;
    }
    __syncthreads();
    float bc = bin[tid];
    for (int n = 0; n < 8; n++) {
        int node = base + n;
        if (node >= N_NODES) break;
        float sum = bc;
#pragma unroll
        for (int k = 0; k < IN_DIM; k++) sum += sx[n * IN_DIM + k] * sW[k * HID + tid];
        g_h[(size_t)node * HID + tid] = sum;
        g_hh[(size_t)node * HID + tid] = __float2half(sum);
    }
}

// ---------------- propagate: fp16 operand gather, f32 accumulate ----------------
__device__ __forceinline__ void fma_h8(float4& acc, float w, uint2 raw) {
    float2 f01 = __half22float2(*reinterpret_cast<__half2*>(&raw.x));
    float2 f23 = __half22float2(*reinterpret_cast<__half2*>(&raw.y));
    acc.x += w * f01.x; acc.y += w * f01.y;
    acc.z += w * f23.x; acc.w += w * f23.y;
}

__global__ void k_gather() {
    int warp = threadIdx.x >> 5, lane = threadIdx.x & 31;
    int d = blockIdx.x * 8 + warp;
    if (d >= N_NODES) return;
    int start = g_off[d], end = g_end[d];
    float dd = g_dis[d];
    const uint2* hh = (const uint2*)g_hh;   // row = 32 x uint2 (4 halfs each)
    float4 acc = make_float4(0.f, 0.f, 0.f, 0.f);
    fma_h8(acc, dd, hh[(size_t)d * 32 + lane]);  // self term
    for (int j = start; j < end; j += 32) {
        int2 ew = make_int2(0, 0);
        if (j + lane < end) ew = g_csr[j + lane];
        int cnt = min(32, end - j);
        int t = 0;
        for (; t + 4 <= cnt; t += 4) {
            int s0 = __shfl_sync(0xffffffffu, ew.x, t);
            int s1 = __shfl_sync(0xffffffffu, ew.x, t + 1);
            int s2 = __shfl_sync(0xffffffffu, ew.x, t + 2);
            int s3 = __shfl_sync(0xffffffffu, ew.x, t + 3);
            float w0 = __int_as_float(__shfl_sync(0xffffffffu, ew.y, t));
            float w1 = __int_as_float(__shfl_sync(0xffffffffu, ew.y, t + 1));
            float w2 = __int_as_float(__shfl_sync(0xffffffffu, ew.y, t + 2));
            float w3 = __int_as_float(__shfl_sync(0xffffffffu, ew.y, t + 3));
            uint2 v0 = hh[(size_t)s0 * 32 + lane];
            uint2 v1 = hh[(size_t)s1 * 32 + lane];
            uint2 v2 = hh[(size_t)s2 * 32 + lane];
            uint2 v3 = hh[(size_t)s3 * 32 + lane];
            fma_h8(acc, w0, v0);
            fma_h8(acc, w1, v1);
            fma_h8(acc, w2, v2);
            fma_h8(acc, w3, v3);
        }
        for (; t < cnt; t++) {
            int   s = __shfl_sync(0xffffffffu, ew.x, t);
            float w = __int_as_float(__shfl_sync(0xffffffffu, ew.y, t));
            fma_h8(acc, w, hh[(size_t)s * 32 + lane]);
        }
    }
    acc.x *= dd; acc.y *= dd; acc.z *= dd; acc.w *= dd;
    ((float4*)g_p)[(size_t)d * 32 + lane] = acc;
}

// ---------------- transform via mma.sync bf16 m16n8k16, dual hi/lo split ----------------
// (R10 structure; epilogue additionally writes fp16 copy when requested)
#define ASTR 68
#define BSTR 136
#define SM_AH 0
#define SM_AL (64 * ASTR)
#define SM_B_U32 (128 * ASTR)
#define SM_U32_TOTAL (128 * ASTR + 64 * BSTR * 2)

__global__ void __launch_bounds__(256, 2) k_transform_bf(
        const float* __restrict__ W, const float* __restrict__ bias,
        const float* __restrict__ gamma, const float* __restrict__ beta,
        float* __restrict__ out, int add_res, int write_half) {
    extern __shared__ uint32_t smem[];
    __shared__ float sBias[HID], sG[HID], sBe[HID];
    __shared__ float psum[2][64], psq[2][64];
    int tid = threadIdx.x;
    int rbase = blockIdx.x * 64;

    for (int i = tid; i < HID; i += 256) {
        sBias[i] = bias[i];
        sG[i] = gamma[i];
        sBe[i] = beta[i];
    }
    {
        ull* sB = (ull*)(smem + SM_B_U32);
        for (int i = tid; i < 64 * HID; i += 256) {
            int kp = i >> 7, n = i & 127;
            uint16_t h0, l0, h1, l1;
            split_bf16(W[(2 * kp) * HID + n], h0, l0);
            split_bf16(W[(2 * kp + 1) * HID + n], h1, l1);
            uint32_t hp = (uint32_t)h0 | ((uint32_t)h1 << 16);
            uint32_t lp = (uint32_t)l0 | ((uint32_t)l1 << 16);
            sB[kp * BSTR + n] = (ull)hp | ((ull)lp << 32);
        }
    }
    {
        const float2* p2 = (const float2*)g_p;
        for (int i = tid; i < 64 * 64; i += 256) {
            int r = i >> 6, kp = i & 63;
            float2 v = p2[(size_t)(rbase + r) * 64 + kp];
            uint16_t h0, l0, h1, l1;
            split_bf16(v.x, h0, l0);
            split_bf16(v.y, h1, l1);
            smem[SM_AH + r * ASTR + kp] = (uint32_t)h0 | ((uint32_t)h1 << 16);
            smem[SM_AL + r * ASTR + kp] = (uint32_t)l0 | ((uint32_t)l1 << 16);
        }
    }
    __syncthreads();

    int warp = tid >> 5, lane = tid & 31;
    int grp = lane >> 2, qid = lane & 3;
    int wr = warp >> 1, wc = warp & 1;
    int row0 = wr * 16;
    int col0 = wc * 64;

    float acc[8][4];
#pragma unroll
    for (int n = 0; n < 8; n++)
#pragma unroll
        for (int c = 0; c < 4; c++) acc[n][c] = 0.f;

    const uint32_t* sAh = smem + SM_AH;
    const uint32_t* sAl = smem + SM_AL;
    const ull* sB = (const ull*)(smem + SM_B_U32);

#pragma unroll 2
    for (int ks = 0; ks < 8; ks++) {
        int kb = 8 * ks;
        int raA = (row0 + grp) * ASTR + kb;
        int raB = raA + 8 * ASTR;
        uint32_t ah[4], al[4];
        ah[0] = sAh[raA + qid];
        ah[1] = sAh[raB + qid];
        ah[2] = sAh[raA + qid + 4];
        ah[3] = sAh[raB + qid + 4];
        al[0] = sAl[raA + qid];
        al[1] = sAl[raB + qid];
        al[2] = sAl[raA + qid + 4];
        al[3] = sAl[raB + qid + 4];

        uint32_t bh0[8], bh1[8], bl0[8], bl1[8];
#pragma unroll
        for (int n = 0; n < 8; n++) {
            ull bv0 = sB[(kb + qid) * BSTR + col0 + n * 8 + grp];
            ull bv1 = sB[(kb + qid + 4) * BSTR + col0 + n * 8 + grp];
            bh0[n] = (uint32_t)bv0; bl0[n] = (uint32_t)(bv0 >> 32);
            bh1[n] = (uint32_t)bv1; bl1[n] = (uint32_t)(bv1 >> 32);
        }
#pragma unroll
        for (int n = 0; n < 8; n++) mma_bf16(acc[n], ah, bh0[n], bh1[n]);
#pragma unroll
        for (int n = 0; n < 8; n++) mma_bf16(acc[n], ah, bl0[n], bl1[n]);
#pragma unroll
        for (int n = 0; n < 8; n++) mma_bf16(acc[n], al, bh0[n], bh1[n]);
    }

    float s[2] = {0.f, 0.f}, q[2] = {0.f, 0.f};
#pragma unroll
    for (int n = 0; n < 8; n++) {
        int c0 = col0 + n * 8 + 2 * qid;
        float b0 = sBias[c0], b1 = sBias[c0 + 1];
        acc[n][0] += b0; acc[n][1] += b1;
        acc[n][2] += b0; acc[n][3] += b1;
        s[0] += acc[n][0] + acc[n][1];
        q[0] += acc[n][0] * acc[n][0] + acc[n][1] * acc[n][1];
        s[1] += acc[n][2] + acc[n][3];
        q[1] += acc[n][2] * acc[n][2] + acc[n][3] * acc[n][3];
    }
#pragma unroll
    for (int o = 1; o <= 2; o <<= 1)
#pragma unroll
        for (int i = 0; i < 2; i++) {
            s[i] += __shfl_xor_sync(0xffffffffu, s[i], o);
            q[i] += __shfl_xor_sync(0xffffffffu, q[i], o);
        }
    if (qid == 0) {
#pragma unroll
        for (int i = 0; i < 2; i++) {
            int r = row0 + grp + i * 8;
            psum[wc][r] = s[i];
            psq[wc][r] = q[i];
        }
    }
    __syncthreads();

    float mu[2], rstd[2];
#pragma unroll
    for (int i = 0; i < 2; i++) {
        int r = row0 + grp + i * 8;
        float tot = psum[0][r] + psum[1][r];
        float tq  = psq[0][r] + psq[1][r];
        mu[i] = tot * (1.f / 128.f);
        rstd[i] = rsqrtf(fmaxf(tq * (1.f / 128.f) - mu[i] * mu[i], 0.f) + LN_EPS);
    }

    int ra = row0 + grp;
    int rb = ra + 8;
    int na = rbase + ra, nb2 = rbase + rb;
    __half2* hh2 = (__half2*)g_hh;
#pragma unroll
    for (int n = 0; n < 8; n++) {
        int c0 = col0 + n * 8 + 2 * qid;
        float g0 = sG[c0], g1 = sG[c0 + 1], e0 = sBe[c0], e1 = sBe[c0 + 1];
        if (na < N_NODES) {
            float2 o;
            o.x = fmaxf((acc[n][0] - mu[0]) * rstd[0] * g0 + e0, 0.f);
            o.y = fmaxf((acc[n][1] - mu[0]) * rstd[0] * g1 + e1, 0.f);
            if (add_res) {
                float2 hp = *(const float2*)(g_h + (size_t)na * HID + c0);
                o.x += hp.x; o.y += hp.y;
            }
            *(float2*)(out + (size_t)na * HID + c0) = o;
            if (write_half) hh2[(size_t)na * 64 + (c0 >> 1)] = __floats2half2_rn(o.x, o.y);
        }
        if (nb2 < N_NODES) {
            float2 o;
            o.x = fmaxf((acc[n][2] - mu[1]) * rstd[1] * g0 + e0, 0.f);
            o.y = fmaxf((acc[n][3] - mu[1]) * rstd[1] * g1 + e1, 0.f);
            if (add_res) {
                float2 hp = *(const float2*)(g_h + (size_t)nb2 * HID + c0);
                o.x += hp.x; o.y += hp.y;
            }
            *(float2*)(out + (size_t)nb2 * HID + c0) = o;
            if (write_half) hh2[(size_t)nb2 * 64 + (c0 >> 1)] = __floats2half2_rn(o.x, o.y);
        }
    }
}

// ---------------- launch ----------------
extern "C" void kernel_launch(void* const* d_in, const int* in_sizes, int n_in,
                              void* d_out, int out_size) {
    const float* x   = (const float*)d_in[0];
    const void*  eix = d_in[1];
    const float* Win = (const float*)d_in[2];
    const float* bin = (const float*)d_in[3];
    const float* Wc  = (const float*)d_in[4];
    const float* bc  = (const float*)d_in[5];
    const float* lg  = (const float*)d_in[6];
    const float* lb  = (const float*)d_in[7];
    int E = in_sizes[1] / 2;

    static bool attr_set = false;  // idempotent attribute set
    if (!attr_set) {
        cudaFuncSetAttribute(k_transform_bf, cudaFuncAttributeMaxDynamicSharedMemorySize,
                             SM_U32_TOTAL * (int)sizeof(uint32_t));
        attr_set = true;
    }

    void* h_addr = nullptr;
    cudaGetSymbolAddress(&h_addr, g_h);

    k_zero_detect<<<(N_NODES + 255) / 256, 256>>>((const unsigned int*)eix, 4096);
    k_hist<<<(E + 255) / 256, 256>>>(eix, E);
    k_alloc<<<(N_NODES + SCAN_B - 1) / SCAN_B, SCAN_B>>>();
    k_fill<<<(E + 255) / 256, 256>>>(eix, E);

    k_proj<<<(N_NODES + 7) / 8, 128>>>(x, Win, bin);

    int tiles = N_ROWS_PAD / 64;  // 1564
    size_t tsmem = SM_U32_TOTAL * sizeof(uint32_t);  // ~104.4KB
    for (int l = 0; l < 3; l++) {
        k_gather<<<(N_NODES + 7) / 8, 256>>>();
        float* out = (l == 2) ? (float*)d_out : (float*)h_addr;
        k_transform_bf<<<tiles, 256, tsmem>>>(
            Wc + (size_t)l * HID * HID, bc + l * HID, lg + l * HID, lb + l * HID,
            out, (l > 0) ? 1 : 0, (l < 2) ? 1 : 0);
    }
}

// round 12
// speedup vs baseline: 1.4575x; 1.0030x over previous
#include <cuda_runtime.h>
#include <cuda_fp16.h>
#include <cstdint>

#define N_NODES 100000
#define N_ROWS_PAD 100096              // 1564 * 64
#define N_EDGES 1600000
#define HID     128
#define IN_DIM  16
#define LN_EPS  1e-5f
#define SCAN_B  512
#define LO_SCALE 2048.0f
#define LO_INV   (1.0f / 2048.0f)

typedef unsigned long long ull;

// ---------------- device scratch ----------------
__device__ int    g_deg[N_NODES];
__device__ float  g_dis[N_NODES];
__device__ int    g_off[N_NODES];
__device__ int    g_end[N_NODES];
__device__ int2   g_csr[N_EDGES];
__device__ float  g_h[(size_t)N_NODES * HID];      // f32 features (residual source)
__device__ __half g_hh[(size_t)N_NODES * HID];     // fp16 features (gather operand)
__device__ __half g_ph[(size_t)N_ROWS_PAD * HID];  // fp16 aggregated (GEMM A), padded zeros
__device__ int    g_total;
__device__ int    g_wide;

// ---------------- fp16 helpers ----------------
__device__ __forceinline__ void split_fp16(float x, uint16_t& hi, uint16_t& lo) {
    __half h = __float2half_rn(x);
    float r = (x - __half2float(h)) * LO_SCALE;   // scaled into fp16 normal range
    __half l = __float2half_rn(r);
    hi = __half_as_ushort(h);
    lo = __half_as_ushort(l);
}
__device__ __forceinline__ void mma_fp16(float c[4], const uint32_t a[4],
                                         uint32_t b0, uint32_t b1) {
    asm("mma.sync.aligned.m16n8k16.row.col.f32.f16.f16.f32 "
        "{%0,%1,%2,%3}, {%4,%5,%6,%7}, {%8,%9}, {%0,%1,%2,%3};"
        : "+f"(c[0]), "+f"(c[1]), "+f"(c[2]), "+f"(c[3])
        : "r"(a[0]), "r"(a[1]), "r"(a[2]), "r"(a[3]), "r"(b0), "r"(b1));
}

// ---------------- zero + edge dtype detection (merged) ----------------
__global__ void k_zero_detect(const unsigned int* __restrict__ e32, int nwords) {
    int i = blockIdx.x * blockDim.x + threadIdx.x;
    if (i < N_NODES) g_deg[i] = 0;
    if (i == 0) g_total = 0;
    if (blockIdx.x == 0) {
        __shared__ unsigned int s_or;
        if (threadIdx.x == 0) s_or = 0u;
        __syncthreads();
        unsigned int v = 0u;
        for (int j = threadIdx.x * 2 + 1; j < nwords; j += blockDim.x * 2) v |= e32[j];
        atomicOr(&s_or, v);
        __syncthreads();
        if (threadIdx.x == 0) g_wide = (s_or == 0u) ? 1 : 0;
    }
}

__device__ __forceinline__ int load_edge(const void* eidx, long idx, int wide) {
    if (wide) return (int)((const long long*)eidx)[idx];
    return ((const int*)eidx)[idx];
}

// ---------------- CSR build ----------------
__global__ void k_hist(const void* __restrict__ eidx, int E) {
    int i = blockIdx.x * blockDim.x + threadIdx.x;
    if (i >= E) return;
    atomicAdd(&g_deg[load_edge(eidx, (long)E + i, g_wide)], 1);
}

__global__ void k_alloc() {
    __shared__ int s[SCAN_B];
    __shared__ int sbase;
    int tid = threadIdx.x;
    int i = blockIdx.x * SCAN_B + tid;
    int v = (i < N_NODES) ? g_deg[i] : 0;
    s[tid] = v;
    __syncthreads();
    for (int o = 1; o < SCAN_B; o <<= 1) {
        int t = (tid >= o) ? s[tid - o] : 0;
        __syncthreads();
        s[tid] += t;
        __syncthreads();
    }
    if (tid == SCAN_B - 1) sbase = atomicAdd(&g_total, s[SCAN_B - 1]);
    __syncthreads();
    int off = sbase + s[tid] - v;
    if (i < N_NODES) {
        g_off[i] = off;
        g_end[i] = off + v;
        g_dis[i] = rsqrtf((float)(v + 1));
        g_deg[i] = off;
    }
}

__global__ void k_fill(const void* __restrict__ eidx, int E) {
    int i = blockIdx.x * blockDim.x + threadIdx.x;
    if (i >= E) return;
    int wide = g_wide;
    int sidx = load_edge(eidx, i, wide);
    int didx = load_edge(eidx, (long)E + i, wide);
    int pos = atomicAdd(&g_deg[didx], 1);
    g_csr[pos] = make_int2(sidx, __float_as_int(g_dis[sidx]));
}

// ---------------- input projection (writes f32 + fp16 copies) ----------------
__global__ void k_proj(const float* __restrict__ x, const float* __restrict__ Win,
                       const float* __restrict__ bin) {
    __shared__ float sW[IN_DIM * HID];
    __shared__ float sx[8 * IN_DIM];
    int tid = threadIdx.x;
    for (int i = tid; i < IN_DIM * HID; i += 128) sW[i] = Win[i];
    int base = blockIdx.x * 8;
    {
        int n = tid / IN_DIM, k = tid % IN_DIM;
        int node = base + n;
        sx[tid] = (node < N_NODES) ? x[(size_t)node * IN_DIM + k] : 0.f;
    }
    __syncthreads();
    float bc = bin[tid];
    for (int n = 0; n < 8; n++) {
        int node = base + n;
        if (node >= N_NODES) break;
        float sum = bc;
#pragma unroll
        for (int k = 0; k < IN_DIM; k++) sum += sx[n * IN_DIM + k] * sW[k * HID + tid];
        g_h[(size_t)node * HID + tid] = sum;
        g_hh[(size_t)node * HID + tid] = __float2half(sum);
    }
}

// ---------------- propagate: fp16 operands, f32 accumulate, fp16 output ----------------
__device__ __forceinline__ void fma_h8(float4& acc, float w, uint2 raw) {
    float2 f01 = __half22float2(*reinterpret_cast<__half2*>(&raw.x));
    float2 f23 = __half22float2(*reinterpret_cast<__half2*>(&raw.y));
    acc.x += w * f01.x; acc.y += w * f01.y;
    acc.z += w * f23.x; acc.w += w * f23.y;
}

__global__ void k_gather() {
    int warp = threadIdx.x >> 5, lane = threadIdx.x & 31;
    int d = blockIdx.x * 8 + warp;
    if (d >= N_NODES) return;
    int start = g_off[d], end = g_end[d];
    float dd = g_dis[d];
    const uint2* hh = (const uint2*)g_hh;
    float4 acc = make_float4(0.f, 0.f, 0.f, 0.f);
    fma_h8(acc, dd, hh[(size_t)d * 32 + lane]);  // self term
    for (int j = start; j < end; j += 32) {
        int2 ew = make_int2(0, 0);
        if (j + lane < end) ew = g_csr[j + lane];
        int cnt = min(32, end - j);
        int t = 0;
        for (; t + 4 <= cnt; t += 4) {
            int s0 = __shfl_sync(0xffffffffu, ew.x, t);
            int s1 = __shfl_sync(0xffffffffu, ew.x, t + 1);
            int s2 = __shfl_sync(0xffffffffu, ew.x, t + 2);
            int s3 = __shfl_sync(0xffffffffu, ew.x, t + 3);
            float w0 = __int_as_float(__shfl_sync(0xffffffffu, ew.y, t));
            float w1 = __int_as_float(__shfl_sync(0xffffffffu, ew.y, t + 1));
            float w2 = __int_as_float(__shfl_sync(0xffffffffu, ew.y, t + 2));
            float w3 = __int_as_float(__shfl_sync(0xffffffffu, ew.y, t + 3));
            uint2 v0 = hh[(size_t)s0 * 32 + lane];
            uint2 v1 = hh[(size_t)s1 * 32 + lane];
            uint2 v2 = hh[(size_t)s2 * 32 + lane];
            uint2 v3 = hh[(size_t)s3 * 32 + lane];
            fma_h8(acc, w0, v0);
            fma_h8(acc, w1, v1);
            fma_h8(acc, w2, v2);
            fma_h8(acc, w3, v3);
        }
        for (; t < cnt; t++) {
            int   s = __shfl_sync(0xffffffffu, ew.x, t);
            float w = __int_as_float(__shfl_sync(0xffffffffu, ew.y, t));
            fma_h8(acc, w, hh[(size_t)s * 32 + lane]);
        }
    }
    acc.x *= dd; acc.y *= dd; acc.z *= dd; acc.w *= dd;
    __half2 o01 = __floats2half2_rn(acc.x, acc.y);
    __half2 o23 = __floats2half2_rn(acc.z, acc.w);
    uint2 st;
    st.x = *reinterpret_cast<uint32_t*>(&o01);
    st.y = *reinterpret_cast<uint32_t*>(&o23);
    ((uint2*)g_ph)[(size_t)d * 32 + lane] = st;
}

// ---------------- transform via mma.sync fp16 m16n8k16 ----------------
// A = fp16(p) unsplit; B = fp16 hi + fp16(lo*2048) in separate accumulator.
// Block: 64-row tile, 256 threads = 8 warps (4 row-groups x 2 col-groups).
// smem (u32): sA [64][68] u32 (half2 pairs), sB [64][136] u64 (bh | bl<<32).
// Total: 17.4KB + 69.6KB = 87KB -> 2 blocks/SM.
#define ASTR 68
#define BSTR 136
#define SM_A 0
#define SM_B_U32 (64 * ASTR)
#define SM_U32_TOTAL (64 * ASTR + 64 * BSTR * 2)

__global__ void __launch_bounds__(256, 2) k_transform_fp(
        const float* __restrict__ W, const float* __restrict__ bias,
        const float* __restrict__ gamma, const float* __restrict__ beta,
        float* __restrict__ out, int add_res, int write_half) {
    extern __shared__ uint32_t smem[];
    __shared__ float sBias[HID], sG[HID], sBe[HID];
    __shared__ float psum[2][64], psq[2][64];
    int tid = threadIdx.x;
    int rbase = blockIdx.x * 64;

    for (int i = tid; i < HID; i += 256) {
        sBias[i] = bias[i];
        sG[i] = gamma[i];
        sBe[i] = beta[i];
    }
    // stage W: sB[kp][n] = (hi(W[2kp][n]),hi(W[2kp+1][n])) | (scaled-lo...)<<32
    {
        ull* sB = (ull*)(smem + SM_B_U32);
        for (int i = tid; i < 64 * HID; i += 256) {
            int kp = i >> 7, n = i & 127;
            uint16_t h0, l0, h1, l1;
            split_fp16(W[(2 * kp) * HID + n], h0, l0);
            split_fp16(W[(2 * kp + 1) * HID + n], h1, l1);
            uint32_t hp = (uint32_t)h0 | ((uint32_t)h1 << 16);
            uint32_t lp = (uint32_t)l0 | ((uint32_t)l1 << 16);
            sB[kp * BSTR + n] = (ull)hp | ((ull)lp << 32);
        }
    }
    // stage A: straight u32 copy of fp16 pairs
    {
        const uint32_t* ph = (const uint32_t*)g_ph;
        for (int i = tid; i < 64 * 64; i += 256) {
            int r = i >> 6, kp = i & 63;
            smem[SM_A + r * ASTR + kp] = ph[(size_t)(rbase + r) * 64 + kp];
        }
    }
    __syncthreads();

    int warp = tid >> 5, lane = tid & 31;
    int grp = lane >> 2, qid = lane & 3;
    int wr = warp >> 1, wc = warp & 1;
    int row0 = wr * 16;
    int col0 = wc * 64;

    float accH[8][4], accL[8][4];
#pragma unroll
    for (int n = 0; n < 8; n++)
#pragma unroll
        for (int c = 0; c < 4; c++) { accH[n][c] = 0.f; accL[n][c] = 0.f; }

    const uint32_t* sA = smem + SM_A;
    const ull* sB = (const ull*)(smem + SM_B_U32);

#pragma unroll 2
    for (int ks = 0; ks < 8; ks++) {
        int kb = 8 * ks;
        int raA = (row0 + grp) * ASTR + kb;
        int raB = raA + 8 * ASTR;
        uint32_t a[4];
        a[0] = sA[raA + qid];
        a[1] = sA[raB + qid];
        a[2] = sA[raA + qid + 4];
        a[3] = sA[raB + qid + 4];
#pragma unroll
        for (int n = 0; n < 8; n++) {
            ull bv0 = sB[(kb + qid) * BSTR + col0 + n * 8 + grp];
            ull bv1 = sB[(kb + qid + 4) * BSTR + col0 + n * 8 + grp];
            // accH/accL independent -> no dependent mma chains
            mma_fp16(accH[n], a, (uint32_t)bv0, (uint32_t)bv1);
            mma_fp16(accL[n], a, (uint32_t)(bv0 >> 32), (uint32_t)(bv1 >> 32));
        }
    }

    // recombine + bias + per-row partial sums
    float acc[8][4];
    float s[2] = {0.f, 0.f}, q[2] = {0.f, 0.f};
#pragma unroll
    for (int n = 0; n < 8; n++) {
        int c0 = col0 + n * 8 + 2 * qid;
        float b0 = sBias[c0], b1 = sBias[c0 + 1];
        acc[n][0] = accH[n][0] + accL[n][0] * LO_INV + b0;
        acc[n][1] = accH[n][1] + accL[n][1] * LO_INV + b1;
        acc[n][2] = accH[n][2] + accL[n][2] * LO_INV + b0;
        acc[n][3] = accH[n][3] + accL[n][3] * LO_INV + b1;
        s[0] += acc[n][0] + acc[n][1];
        q[0] += acc[n][0] * acc[n][0] + acc[n][1] * acc[n][1];
        s[1] += acc[n][2] + acc[n][3];
        q[1] += acc[n][2] * acc[n][2] + acc[n][3] * acc[n][3];
    }
#pragma unroll
    for (int o = 1; o <= 2; o <<= 1)
#pragma unroll
        for (int i = 0; i < 2; i++) {
            s[i] += __shfl_xor_sync(0xffffffffu, s[i], o);
            q[i] += __shfl_xor_sync(0xffffffffu, q[i], o);
        }
    if (qid == 0) {
#pragma unroll
        for (int i = 0; i < 2; i++) {
            int r = row0 + grp + i * 8;
            psum[wc][r] = s[i];
            psq[wc][r] = q[i];
        }
    }
    __syncthreads();

    float mu[2], rstd[2];
#pragma unroll
    for (int i = 0; i < 2; i++) {
        int r = row0 + grp + i * 8;
        float tot = psum[0][r] + psum[1][r];
        float tq  = psq[0][r] + psq[1][r];
        mu[i] = tot * (1.f / 128.f);
        rstd[i] = rsqrtf(fmaxf(tq * (1.f / 128.f) - mu[i] * mu[i], 0.f) + LN_EPS);
    }

    int ra = row0 + grp;
    int rb = ra + 8;
    int na = rbase + ra, nb2 = rbase + rb;
    __half2* hh2 = (__half2*)g_hh;
#pragma unroll
    for (int n = 0; n < 8; n++) {
        int c0 = col0 + n * 8 + 2 * qid;
        float g0 = sG[c0], g1 = sG[c0 + 1], e0 = sBe[c0], e1 = sBe[c0 + 1];
        if (na < N_NODES) {
            float2 o;
            o.x = fmaxf((acc[n][0] - mu[0]) * rstd[0] * g0 + e0, 0.f);
            o.y = fmaxf((acc[n][1] - mu[0]) * rstd[0] * g1 + e1, 0.f);
            if (add_res) {
                float2 hp = *(const float2*)(g_h + (size_t)na * HID + c0);
                o.x += hp.x; o.y += hp.y;
            }
            *(float2*)(out + (size_t)na * HID + c0) = o;
            if (write_half) hh2[(size_t)na * 64 + (c0 >> 1)] = __floats2half2_rn(o.x, o.y);
        }
        if (nb2 < N_NODES) {
            float2 o;
            o.x = fmaxf((acc[n][2] - mu[1]) * rstd[1] * g0 + e0, 0.f);
            o.y = fmaxf((acc[n][3] - mu[1]) * rstd[1] * g1 + e1, 0.f);
            if (add_res) {
                float2 hp = *(const float2*)(g_h + (size_t)nb2 * HID + c0);
                o.x += hp.x; o.y += hp.y;
            }
            *(float2*)(out + (size_t)nb2 * HID + c0) = o;
            if (write_half) hh2[(size_t)nb2 * 64 + (c0 >> 1)] = __floats2half2_rn(o.x, o.y);
        }
    }
}

// ---------------- launch ----------------
extern "C" void kernel_launch(void* const* d_in, const int* in_sizes, int n_in,
                              void* d_out, int out_size) {
    const float* x   = (const float*)d_in[0];
    const void*  eix = d_in[1];
    const float* Win = (const float*)d_in[2];
    const float* bin = (const float*)d_in[3];
    const float* Wc  = (const float*)d_in[4];
    const float* bc  = (const float*)d_in[5];
    const float* lg  = (const float*)d_in[6];
    const float* lb  = (const float*)d_in[7];
    int E = in_sizes[1] / 2;

    static bool attr_set = false;  // idempotent attribute set
    if (!attr_set) {
        cudaFuncSetAttribute(k_transform_fp, cudaFuncAttributeMaxDynamicSharedMemorySize,
                             SM_U32_TOTAL * (int)sizeof(uint32_t));
        attr_set = true;
    }

    void* h_addr = nullptr;
    cudaGetSymbolAddress(&h_addr, g_h);

    k_zero_detect<<<(N_NODES + 255) / 256, 256>>>((const unsigned int*)eix, 4096);
    k_hist<<<(E + 255) / 256, 256>>>(eix, E);
    k_alloc<<<(N_NODES + SCAN_B - 1) / SCAN_B, SCAN_B>>>();
    k_fill<<<(E + 255) / 256, 256>>>(eix, E);

    k_proj<<<(N_NODES + 7) / 8, 128>>>(x, Win, bin);

    int tiles = N_ROWS_PAD / 64;  // 1564
    size_t tsmem = SM_U32_TOTAL * sizeof(uint32_t);  // ~87KB
    for (int l = 0; l < 3; l++) {
        k_gather<<<(N_NODES + 7) / 8, 256>>>();
        float* out = (l == 2) ? (float*)d_out : (float*)h_addr;
        k_transform_fp<<<tiles, 256, tsmem>>>(
            Wc + (size_t)l * HID * HID, bc + l * HID, lg + l * HID, lb + l * HID,
            out, (l > 0) ? 1 : 0, (l < 2) ? 1 : 0);
    }
}